// round 1
// baseline (speedup 1.0000x reference)
#include <cuda_runtime.h>
#include <cuda_bf16.h>
#include <math.h>

// Problem constants (fixed by the reference)
#define D_MODEL 1024
#define DKH     64
#define NH      16
#define BATCH   4
#define SEQ     2048
#define MROWS   (BATCH * SEQ)   // 8192

// Scratch (device globals: allocation-free per harness rules)
__device__ float g_q[(size_t)MROWS * D_MODEL];
__device__ float g_k[(size_t)MROWS * D_MODEL];
__device__ float g_v[(size_t)MROWS * D_MODEL];
__device__ float g_a[(size_t)MROWS * D_MODEL];

// ---------------------------------------------------------------------------
// GEMM: C[M,N] = X[M,K] * W[N,K]^T  (+ optional bias[N])
// Both operands K-major => symmetric transposed smem tiles.
// 128x128 block tile, BK=16, 256 threads, 8x8 per thread.
// ---------------------------------------------------------------------------
__global__ __launch_bounds__(256, 2)
void gemm_tn(const float* __restrict__ X, const float* __restrict__ W,
             const float* __restrict__ bias, float* __restrict__ C,
             int M, int N, int K, int addBias)
{
    __shared__ float As[16][132];
    __shared__ float Bs[16][132];

    const int tid = threadIdx.x;
    const int m0 = blockIdx.y * 128;
    const int n0 = blockIdx.x * 128;
    const int ty = tid >> 4;        // 0..15 -> rows ty*8..+7
    const int tx = tid & 15;        // 0..15 -> cols tx*8..+7
    const int lr = tid >> 2;        // 0..63
    const int lc = (tid & 3) << 2;  // 0,4,8,12

    float acc[8][8];
#pragma unroll
    for (int i = 0; i < 8; ++i)
#pragma unroll
        for (int j = 0; j < 8; ++j) acc[i][j] = 0.f;

    const float* Xp  = X + (size_t)(m0 + lr) * K + lc;
    const float* Xp2 = Xp + (size_t)64 * K;
    const float* Wp  = W + (size_t)(n0 + lr) * K + lc;
    const float* Wp2 = Wp + (size_t)64 * K;

    for (int k0 = 0; k0 < K; k0 += 16) {
        float4 a0 = *(const float4*)(Xp  + k0);
        float4 a1 = *(const float4*)(Xp2 + k0);
        float4 b0 = *(const float4*)(Wp  + k0);
        float4 b1 = *(const float4*)(Wp2 + k0);

        __syncthreads();
        As[lc + 0][lr]      = a0.x; As[lc + 1][lr]      = a0.y;
        As[lc + 2][lr]      = a0.z; As[lc + 3][lr]      = a0.w;
        As[lc + 0][lr + 64] = a1.x; As[lc + 1][lr + 64] = a1.y;
        As[lc + 2][lr + 64] = a1.z; As[lc + 3][lr + 64] = a1.w;
        Bs[lc + 0][lr]      = b0.x; Bs[lc + 1][lr]      = b0.y;
        Bs[lc + 2][lr]      = b0.z; Bs[lc + 3][lr]      = b0.w;
        Bs[lc + 0][lr + 64] = b1.x; Bs[lc + 1][lr + 64] = b1.y;
        Bs[lc + 2][lr + 64] = b1.z; Bs[lc + 3][lr + 64] = b1.w;
        __syncthreads();

#pragma unroll
        for (int k = 0; k < 16; ++k) {
            float4 ar0 = *(const float4*)&As[k][ty * 8];
            float4 ar1 = *(const float4*)&As[k][ty * 8 + 4];
            float4 br0 = *(const float4*)&Bs[k][tx * 8];
            float4 br1 = *(const float4*)&Bs[k][tx * 8 + 4];
            float a[8] = {ar0.x, ar0.y, ar0.z, ar0.w, ar1.x, ar1.y, ar1.z, ar1.w};
            float b[8] = {br0.x, br0.y, br0.z, br0.w, br1.x, br1.y, br1.z, br1.w};
#pragma unroll
            for (int i = 0; i < 8; ++i)
#pragma unroll
                for (int j = 0; j < 8; ++j)
                    acc[i][j] = fmaf(a[i], b[j], acc[i][j]);
        }
    }

    float badd[8];
#pragma unroll
    for (int j = 0; j < 8; ++j)
        badd[j] = addBias ? bias[n0 + tx * 8 + j] : 0.f;

#pragma unroll
    for (int i = 0; i < 8; ++i) {
        const int row = m0 + ty * 8 + i;
        float4 o0, o1;
        o0.x = acc[i][0] + badd[0]; o0.y = acc[i][1] + badd[1];
        o0.z = acc[i][2] + badd[2]; o0.w = acc[i][3] + badd[3];
        o1.x = acc[i][4] + badd[4]; o1.y = acc[i][5] + badd[5];
        o1.z = acc[i][6] + badd[6]; o1.w = acc[i][7] + badd[7];
        *(float4*)&C[(size_t)row * N + n0 + tx * 8]     = o0;
        *(float4*)&C[(size_t)row * N + n0 + tx * 8 + 4] = o1;
    }
}

// ---------------------------------------------------------------------------
// Causal flash attention, per (batch, head). BQ = BK = 64, dk = 64.
// 128 threads: ty = tid/8 owns 4 query rows, tx = tid%8 owns 8 cols.
// Q/K stored transposed [d][row] in smem; K tile smem reused for P tile.
// ---------------------------------------------------------------------------
#define QP 65   // pitch for QsT / KsT / Ps (odd -> conflict-light)
#define VP 68   // pitch for Vs (multiple of 4 for float4)
#define FLASH_SMEM ((64 * QP * 2 + 64 * VP) * 4)

__global__ __launch_bounds__(128)
void flash_kernel(const float* __restrict__ Q, const float* __restrict__ K,
                  const float* __restrict__ V, float* __restrict__ A)
{
    extern __shared__ float sm[];
    float* QsT = sm;                  // [d][row], pitch QP
    float* KsT = sm + 64 * QP;        // [d][col], pitch QP; reused as Ps[row][k]
    float* Vs  = sm + 2 * 64 * QP;    // [k][dcol], pitch VP

    const int tid = threadIdx.x;
    const int ty = tid >> 3;          // 0..15, query rows ty*4 + i
    const int tx = tid & 7;           // 0..7,  cols tx*8 + j
    const int qb = gridDim.x - 1 - blockIdx.x;  // heavy blocks first
    const int bh = blockIdx.y;
    const int b = bh >> 4, h = bh & 15;

    const size_t headoff = (size_t)b * SEQ * D_MODEL + (size_t)h * DKH;
    const float* Qh = Q + headoff;
    const float* Kh = K + headoff;
    const float* Vh = V + headoff;

    // Load Q tile transposed: QsT[d][r]
    for (int idx = tid; idx < 64 * 16; idx += 128) {
        int r  = idx >> 4;
        int dq = (idx & 15) << 2;
        float4 t = *(const float4*)&Qh[(size_t)(qb * 64 + r) * D_MODEL + dq];
        QsT[(dq + 0) * QP + r] = t.x;
        QsT[(dq + 1) * QP + r] = t.y;
        QsT[(dq + 2) * QP + r] = t.z;
        QsT[(dq + 3) * QP + r] = t.w;
    }

    float m_i[4], l_i[4], o[4][8];
#pragma unroll
    for (int i = 0; i < 4; ++i) {
        m_i[i] = -1e30f; l_i[i] = 0.f;
#pragma unroll
        for (int j = 0; j < 8; ++j) o[i][j] = 0.f;
    }

    for (int kb = 0; kb <= qb; ++kb) {
        // also guarantees Q tile visible before first score pass, and prior
        // PV reads of Ps/Vs complete before overwrite
        __syncthreads();
        for (int idx = tid; idx < 64 * 16; idx += 128) {
            int r  = idx >> 4;
            int dq = (idx & 15) << 2;
            float4 t = *(const float4*)&Kh[(size_t)(kb * 64 + r) * D_MODEL + dq];
            KsT[(dq + 0) * QP + r] = t.x;
            KsT[(dq + 1) * QP + r] = t.y;
            KsT[(dq + 2) * QP + r] = t.z;
            KsT[(dq + 3) * QP + r] = t.w;
            float4 u = *(const float4*)&Vh[(size_t)(kb * 64 + r) * D_MODEL + dq];
            *(float4*)&Vs[r * VP + dq] = u;
        }
        __syncthreads();

        // S = Q K^T
        float s[4][8];
#pragma unroll
        for (int i = 0; i < 4; ++i)
#pragma unroll
            for (int j = 0; j < 8; ++j) s[i][j] = 0.f;

#pragma unroll 4
        for (int d = 0; d < 64; ++d) {
            float a0 = QsT[d * QP + ty * 4 + 0];
            float a1 = QsT[d * QP + ty * 4 + 1];
            float a2 = QsT[d * QP + ty * 4 + 2];
            float a3 = QsT[d * QP + ty * 4 + 3];
            float bb[8];
#pragma unroll
            for (int j = 0; j < 8; ++j) bb[j] = KsT[d * QP + tx * 8 + j];
#pragma unroll
            for (int j = 0; j < 8; ++j) {
                s[0][j] = fmaf(a0, bb[j], s[0][j]);
                s[1][j] = fmaf(a1, bb[j], s[1][j]);
                s[2][j] = fmaf(a2, bb[j], s[2][j]);
                s[3][j] = fmaf(a3, bb[j], s[3][j]);
            }
        }

        // scale + causal mask (only the diagonal tile needs masking)
        const bool diag = (kb == qb);
#pragma unroll
        for (int i = 0; i < 4; ++i) {
            const int qg = qb * 64 + ty * 4 + i;
#pragma unroll
            for (int j = 0; j < 8; ++j) {
                float v = s[i][j] * 0.125f;
                if (diag && (kb * 64 + tx * 8 + j > qg)) v = -1e30f;
                s[i][j] = v;
            }
        }

        // online softmax update (row groups span 8 consecutive lanes)
#pragma unroll
        for (int i = 0; i < 4; ++i) {
            float mx = s[i][0];
#pragma unroll
            for (int j = 1; j < 8; ++j) mx = fmaxf(mx, s[i][j]);
            mx = fmaxf(mx, __shfl_xor_sync(0xffffffffu, mx, 1));
            mx = fmaxf(mx, __shfl_xor_sync(0xffffffffu, mx, 2));
            mx = fmaxf(mx, __shfl_xor_sync(0xffffffffu, mx, 4));
            const float mnew = fmaxf(m_i[i], mx);
            const float corr = __expf(m_i[i] - mnew);
            m_i[i] = mnew;
            float rs = 0.f;
#pragma unroll
            for (int j = 0; j < 8; ++j) {
                float p = __expf(s[i][j] - mnew);
                s[i][j] = p;
                rs += p;
            }
            rs += __shfl_xor_sync(0xffffffffu, rs, 1);
            rs += __shfl_xor_sync(0xffffffffu, rs, 2);
            rs += __shfl_xor_sync(0xffffffffu, rs, 4);
            l_i[i] = l_i[i] * corr + rs;
#pragma unroll
            for (int j = 0; j < 8; ++j) o[i][j] *= corr;
        }

        __syncthreads();   // done reading KsT as K
        // write P over KsT: Ps[row][k]
#pragma unroll
        for (int i = 0; i < 4; ++i)
#pragma unroll
            for (int j = 0; j < 8; ++j)
                KsT[(ty * 4 + i) * QP + tx * 8 + j] = s[i][j];
        __syncthreads();

        // O += P V
#pragma unroll 4
        for (int k = 0; k < 64; ++k) {
            float p0 = KsT[(ty * 4 + 0) * QP + k];
            float p1 = KsT[(ty * 4 + 1) * QP + k];
            float p2 = KsT[(ty * 4 + 2) * QP + k];
            float p3 = KsT[(ty * 4 + 3) * QP + k];
            float4 v0 = *(const float4*)&Vs[k * VP + tx * 8];
            float4 v1 = *(const float4*)&Vs[k * VP + tx * 8 + 4];
            float vv[8] = {v0.x, v0.y, v0.z, v0.w, v1.x, v1.y, v1.z, v1.w};
#pragma unroll
            for (int j = 0; j < 8; ++j) {
                o[0][j] = fmaf(p0, vv[j], o[0][j]);
                o[1][j] = fmaf(p1, vv[j], o[1][j]);
                o[2][j] = fmaf(p2, vv[j], o[2][j]);
                o[3][j] = fmaf(p3, vv[j], o[3][j]);
            }
        }
    }

    // epilogue: normalize, write to (b, s, h*64 + d) layout
    float* Ah = A + headoff;
#pragma unroll
    for (int i = 0; i < 4; ++i) {
        const float inv = 1.f / l_i[i];
        const int row = qb * 64 + ty * 4 + i;
        float4 r0, r1;
        r0.x = o[i][0] * inv; r0.y = o[i][1] * inv;
        r0.z = o[i][2] * inv; r0.w = o[i][3] * inv;
        r1.x = o[i][4] * inv; r1.y = o[i][5] * inv;
        r1.z = o[i][6] * inv; r1.w = o[i][7] * inv;
        *(float4*)&Ah[(size_t)row * D_MODEL + tx * 8]     = r0;
        *(float4*)&Ah[(size_t)row * D_MODEL + tx * 8 + 4] = r1;
    }
}

// ---------------------------------------------------------------------------
extern "C" void kernel_launch(void* const* d_in, const int* in_sizes, int n_in,
                              void* d_out, int out_size)
{
    const float* xq = (const float*)d_in[0];
    const float* xk = (const float*)d_in[1];
    const float* xv = (const float*)d_in[2];
    const float* wq = (const float*)d_in[3];
    const float* wk = (const float*)d_in[4];
    const float* wv = (const float*)d_in[5];
    const float* wp = (const float*)d_in[6];
    const float* bp = (const float*)d_in[7];
    float* out = (float*)d_out;

    float *gq, *gk, *gv, *ga;
    cudaGetSymbolAddress((void**)&gq, g_q);
    cudaGetSymbolAddress((void**)&gk, g_k);
    cudaGetSymbolAddress((void**)&gv, g_v);
    cudaGetSymbolAddress((void**)&ga, g_a);

    cudaFuncSetAttribute(flash_kernel,
                         cudaFuncAttributeMaxDynamicSharedMemorySize, FLASH_SMEM);

    dim3 gg(D_MODEL / 128, MROWS / 128);   // (8, 64)
    gemm_tn<<<gg, 256>>>(xq, wq, nullptr, gq, MROWS, D_MODEL, D_MODEL, 0);
    gemm_tn<<<gg, 256>>>(xk, wk, nullptr, gk, MROWS, D_MODEL, D_MODEL, 0);
    gemm_tn<<<gg, 256>>>(xv, wv, nullptr, gv, MROWS, D_MODEL, D_MODEL, 0);

    flash_kernel<<<dim3(SEQ / 64, BATCH * NH), 128, FLASH_SMEM>>>(gq, gk, gv, ga);

    gemm_tn<<<gg, 256>>>(ga, wp, bp, out, MROWS, D_MODEL, D_MODEL, 1);
}

// round 7
// speedup vs baseline: 1.4296x; 1.4296x over previous
#include <cuda_runtime.h>
#include <cuda_bf16.h>
#include <cstdint>
#include <math.h>

// Problem constants
#define D_MODEL 1024
#define DKH     64
#define NH      16
#define BATCH   4
#define SEQ     2048
#define MROWS   (BATCH * SEQ)   // 8192

// Scratch (device globals: allocation-free per harness rules)
__device__ float g_q[(size_t)MROWS * D_MODEL];
__device__ float g_k[(size_t)MROWS * D_MODEL];
__device__ float g_v[(size_t)MROWS * D_MODEL];
__device__ float g_a[(size_t)MROWS * D_MODEL];
// tf32-rounded GEMM inputs
__device__ float g_rxq[(size_t)MROWS * D_MODEL];
__device__ float g_rxk[(size_t)MROWS * D_MODEL];
__device__ float g_rxv[(size_t)MROWS * D_MODEL];
__device__ float g_rwq[(size_t)D_MODEL * D_MODEL];
__device__ float g_rwk[(size_t)D_MODEL * D_MODEL];
__device__ float g_rwv[(size_t)D_MODEL * D_MODEL];
__device__ float g_rwp[(size_t)D_MODEL * D_MODEL];

// ---------------------------------------------------------------------------
// Helpers (baseline PTX only — no tcgen05 / 'a'-features: harness compiles
// at compute_103, which rejects arch-specific instructions)
// ---------------------------------------------------------------------------
__device__ __forceinline__ uint32_t smem_u32(const void* p) {
    uint32_t a;
    asm("{ .reg .u64 t; cvta.to.shared.u64 t, %1; cvt.u32.u64 %0, t; }"
        : "=r"(a) : "l"(p));
    return a;
}
__device__ __forceinline__ float tf32r(float x) {
    uint32_t u;
    asm("cvt.rna.tf32.f32 %0, %1;" : "=r"(u) : "f"(x));
    return __uint_as_float(u);
}

#define CP_ASYNC16(dst, src) \
    asm volatile("cp.async.cg.shared.global [%0], [%1], 16;" :: "r"(dst), "l"(src))
#define CP_COMMIT() asm volatile("cp.async.commit_group;")
#define CP_WAIT(n)  asm volatile("cp.async.wait_group %0;" :: "n"(n))

// mma.sync m16n8k8 tf32: D = A*B + C (A row-major 16x8, B col-major 8x8)
#define MMA_TF32(c0, c1, c2, c3, a0, a1, a2, a3, b0, b1)                      \
    asm volatile(                                                             \
        "mma.sync.aligned.m16n8k8.row.col.f32.tf32.tf32.f32 "                 \
        "{%0,%1,%2,%3}, {%4,%5,%6,%7}, {%8,%9}, {%0,%1,%2,%3};"               \
        : "+f"(c0), "+f"(c1), "+f"(c2), "+f"(c3)                              \
        : "r"(a0), "r"(a1), "r"(a2), "r"(a3), "r"(b0), "r"(b1))

// ---------------------------------------------------------------------------
// tf32 pre-round pass
// ---------------------------------------------------------------------------
__global__ void round_tf32_kernel(const float* __restrict__ x,
                                  float* __restrict__ y, int n4)
{
    int i = blockIdx.x * blockDim.x + threadIdx.x;
    if (i < n4) {
        float4 v = ((const float4*)x)[i];
        v.x = tf32r(v.x); v.y = tf32r(v.y); v.z = tf32r(v.z); v.w = tf32r(v.w);
        ((float4*)y)[i] = v;
    }
}

// ---------------------------------------------------------------------------
// tf32 mma.sync GEMM: C[M,N] = X[M,K] * W[N,K]^T (+bias). M=8192, N=K=1024.
// CTA tile 128x128, 8 warps (2m x 4n), warp tile 64x32, BK=16,
// 4-stage cp.async pipeline. Smem rows pitch 20 floats: 16B-aligned rows for
// cp.async AND conflict-free mma fragment loads (banks (20g+tig)%32 distinct).
// ---------------------------------------------------------------------------
#define BK      16
#define PITCH   20
#define ATILE   (128 * PITCH)           // floats per operand tile
#define STAGEF  (2 * ATILE)             // floats per stage (A + B)
#define NSTAGE  4
#define GEMM_SMEM (NSTAGE * STAGEF * 4) // 81920 bytes
#define NCH     (D_MODEL / BK)          // 64 k-chunks

__global__ __launch_bounds__(256, 1)
void gemm_mma(const float* __restrict__ X, const float* __restrict__ W,
              const float* __restrict__ bias, float* __restrict__ C, int addBias)
{
    extern __shared__ float smf[];
    const int tid  = threadIdx.x;
    const int wid  = tid >> 5;
    const int lane = tid & 31;
    const int g    = lane >> 2;         // groupID 0..7
    const int tig  = lane & 3;          // thread-in-group 0..3
    const int m0 = blockIdx.y * 128;
    const int n0 = blockIdx.x * 128;
    const int wm = (wid >> 2) * 64;     // warp m offset (0 or 64)
    const int wn = (wid & 3) * 32;      // warp n offset (0/32/64/96)

    float c[4][4][4];                   // [mt][nt][reg]
#pragma unroll
    for (int mt = 0; mt < 4; ++mt)
#pragma unroll
        for (int nt = 0; nt < 4; ++nt)
#pragma unroll
            for (int r = 0; r < 4; ++r) c[mt][nt][r] = 0.f;

    // producer: load k-chunk kt into stage kt % NSTAGE
    //   1024 x 16B copies per stage, 4 per thread
#define LOAD_STAGE(kt) do {                                                    \
        float* st = smf + ((kt) % NSTAGE) * STAGEF;                            \
        const int k0 = (kt) * BK;                                              \
        _Pragma("unroll")                                                      \
        for (int i = 0; i < 4; ++i) {                                          \
            const int idx  = i * 256 + tid;                                    \
            const int isB  = idx >> 9;                                         \
            const int row  = (idx >> 2) & 127;                                 \
            const int quad = idx & 3;                                          \
            float* dst = st + isB * ATILE + row * PITCH + quad * 4;            \
            const float* src = (isB ? W + (size_t)(n0 + row) * D_MODEL        \
                                    : X + (size_t)(m0 + row) * D_MODEL)       \
                               + k0 + quad * 4;                                \
            CP_ASYNC16(smem_u32(dst), src);                                    \
        }                                                                      \
        CP_COMMIT();                                                           \
    } while (0)

    LOAD_STAGE(0); LOAD_STAGE(1); LOAD_STAGE(2);

    for (int kt = 0; kt < NCH; ++kt) {
        if (kt < NCH - 2)       CP_WAIT(2);
        else if (kt == NCH - 2) CP_WAIT(1);
        else                    CP_WAIT(0);
        __syncthreads();

        if (kt + 3 < NCH) LOAD_STAGE(kt + 3);

        const float* As = smf + (kt % NSTAGE) * STAGEF;
        const float* Bs = As + ATILE;

#pragma unroll
        for (int ks = 0; ks < 2; ++ks) {
            const int kb = ks * 8;
            uint32_t a[4][4], b[4][2];
#pragma unroll
            for (int mt = 0; mt < 4; ++mt) {
                const float* ap = As + (wm + mt * 16 + g) * PITCH + kb + tig;
                a[mt][0] = __float_as_uint(ap[0]);
                a[mt][1] = __float_as_uint(ap[8 * PITCH]);
                a[mt][2] = __float_as_uint(ap[4]);
                a[mt][3] = __float_as_uint(ap[8 * PITCH + 4]);
            }
#pragma unroll
            for (int nt = 0; nt < 4; ++nt) {
                const float* bp = Bs + (wn + nt * 8 + g) * PITCH + kb + tig;
                b[nt][0] = __float_as_uint(bp[0]);
                b[nt][1] = __float_as_uint(bp[4]);
            }
#pragma unroll
            for (int mt = 0; mt < 4; ++mt)
#pragma unroll
                for (int nt = 0; nt < 4; ++nt)
                    MMA_TF32(c[mt][nt][0], c[mt][nt][1], c[mt][nt][2], c[mt][nt][3],
                             a[mt][0], a[mt][1], a[mt][2], a[mt][3],
                             b[nt][0], b[nt][1]);
        }
    }

    // epilogue: c0/c1 -> (row, col..col+1), c2/c3 -> (row+8, ...)
#pragma unroll
    for (int mt = 0; mt < 4; ++mt) {
        const int row = m0 + wm + mt * 16 + g;
#pragma unroll
        for (int nt = 0; nt < 4; ++nt) {
            const int col = n0 + wn + nt * 8 + 2 * tig;
            float b0 = 0.f, b1 = 0.f;
            if (addBias) { b0 = bias[col]; b1 = bias[col + 1]; }
            float2 v0 = make_float2(c[mt][nt][0] + b0, c[mt][nt][1] + b1);
            float2 v1 = make_float2(c[mt][nt][2] + b0, c[mt][nt][3] + b1);
            *(float2*)&C[(size_t)row * D_MODEL + col]       = v0;
            *(float2*)&C[(size_t)(row + 8) * D_MODEL + col] = v1;
        }
    }
#undef LOAD_STAGE
}

// ---------------------------------------------------------------------------
// Causal flash attention (unchanged; epilogue rounds to tf32 for final GEMM)
// ---------------------------------------------------------------------------
#define QP 65
#define VP 68
#define FLASH_SMEM ((64 * QP * 2 + 64 * VP) * 4)

__global__ __launch_bounds__(128)
void flash_kernel(const float* __restrict__ Q, const float* __restrict__ K,
                  const float* __restrict__ V, float* __restrict__ A)
{
    extern __shared__ float sm[];
    float* QsT = sm;
    float* KsT = sm + 64 * QP;
    float* Vs  = sm + 2 * 64 * QP;

    const int tid = threadIdx.x;
    const int ty = tid >> 3;
    const int tx = tid & 7;
    const int qb = gridDim.x - 1 - blockIdx.x;
    const int bh = blockIdx.y;
    const int b = bh >> 4, h = bh & 15;

    const size_t headoff = (size_t)b * SEQ * D_MODEL + (size_t)h * DKH;
    const float* Qh = Q + headoff;
    const float* Kh = K + headoff;
    const float* Vh = V + headoff;

    for (int idx = tid; idx < 64 * 16; idx += 128) {
        int r  = idx >> 4;
        int dq = (idx & 15) << 2;
        float4 t = *(const float4*)&Qh[(size_t)(qb * 64 + r) * D_MODEL + dq];
        QsT[(dq + 0) * QP + r] = t.x;
        QsT[(dq + 1) * QP + r] = t.y;
        QsT[(dq + 2) * QP + r] = t.z;
        QsT[(dq + 3) * QP + r] = t.w;
    }

    float m_i[4], l_i[4], o[4][8];
#pragma unroll
    for (int i = 0; i < 4; ++i) {
        m_i[i] = -1e30f; l_i[i] = 0.f;
#pragma unroll
        for (int j = 0; j < 8; ++j) o[i][j] = 0.f;
    }

    for (int kb = 0; kb <= qb; ++kb) {
        __syncthreads();
        for (int idx = tid; idx < 64 * 16; idx += 128) {
            int r  = idx >> 4;
            int dq = (idx & 15) << 2;
            float4 t = *(const float4*)&Kh[(size_t)(kb * 64 + r) * D_MODEL + dq];
            KsT[(dq + 0) * QP + r] = t.x;
            KsT[(dq + 1) * QP + r] = t.y;
            KsT[(dq + 2) * QP + r] = t.z;
            KsT[(dq + 3) * QP + r] = t.w;
            float4 u = *(const float4*)&Vh[(size_t)(kb * 64 + r) * D_MODEL + dq];
            *(float4*)&Vs[r * VP + dq] = u;
        }
        __syncthreads();

        float s[4][8];
#pragma unroll
        for (int i = 0; i < 4; ++i)
#pragma unroll
            for (int j = 0; j < 8; ++j) s[i][j] = 0.f;

#pragma unroll 4
        for (int d = 0; d < 64; ++d) {
            float a0 = QsT[d * QP + ty * 4 + 0];
            float a1 = QsT[d * QP + ty * 4 + 1];
            float a2 = QsT[d * QP + ty * 4 + 2];
            float a3 = QsT[d * QP + ty * 4 + 3];
            float bb[8];
#pragma unroll
            for (int j = 0; j < 8; ++j) bb[j] = KsT[d * QP + tx * 8 + j];
#pragma unroll
            for (int j = 0; j < 8; ++j) {
                s[0][j] = fmaf(a0, bb[j], s[0][j]);
                s[1][j] = fmaf(a1, bb[j], s[1][j]);
                s[2][j] = fmaf(a2, bb[j], s[2][j]);
                s[3][j] = fmaf(a3, bb[j], s[3][j]);
            }
        }

        const bool diag = (kb == qb);
#pragma unroll
        for (int i = 0; i < 4; ++i) {
            const int qg = qb * 64 + ty * 4 + i;
#pragma unroll
            for (int j = 0; j < 8; ++j) {
                float v = s[i][j] * 0.125f;
                if (diag && (kb * 64 + tx * 8 + j > qg)) v = -1e30f;
                s[i][j] = v;
            }
        }

#pragma unroll
        for (int i = 0; i < 4; ++i) {
            float mx = s[i][0];
#pragma unroll
            for (int j = 1; j < 8; ++j) mx = fmaxf(mx, s[i][j]);
            mx = fmaxf(mx, __shfl_xor_sync(0xffffffffu, mx, 1));
            mx = fmaxf(mx, __shfl_xor_sync(0xffffffffu, mx, 2));
            mx = fmaxf(mx, __shfl_xor_sync(0xffffffffu, mx, 4));
            const float mnew = fmaxf(m_i[i], mx);
            const float corr = __expf(m_i[i] - mnew);
            m_i[i] = mnew;
            float rs = 0.f;
#pragma unroll
            for (int j = 0; j < 8; ++j) {
                float p = __expf(s[i][j] - mnew);
                s[i][j] = p;
                rs += p;
            }
            rs += __shfl_xor_sync(0xffffffffu, rs, 1);
            rs += __shfl_xor_sync(0xffffffffu, rs, 2);
            rs += __shfl_xor_sync(0xffffffffu, rs, 4);
            l_i[i] = l_i[i] * corr + rs;
#pragma unroll
            for (int j = 0; j < 8; ++j) o[i][j] *= corr;
        }

        __syncthreads();
#pragma unroll
        for (int i = 0; i < 4; ++i)
#pragma unroll
            for (int j = 0; j < 8; ++j)
                KsT[(ty * 4 + i) * QP + tx * 8 + j] = s[i][j];
        __syncthreads();

#pragma unroll 4
        for (int k = 0; k < 64; ++k) {
            float p0 = KsT[(ty * 4 + 0) * QP + k];
            float p1 = KsT[(ty * 4 + 1) * QP + k];
            float p2 = KsT[(ty * 4 + 2) * QP + k];
            float p3 = KsT[(ty * 4 + 3) * QP + k];
            float4 v0 = *(const float4*)&Vs[k * VP + tx * 8];
            float4 v1 = *(const float4*)&Vs[k * VP + tx * 8 + 4];
            float vv[8] = {v0.x, v0.y, v0.z, v0.w, v1.x, v1.y, v1.z, v1.w};
#pragma unroll
            for (int j = 0; j < 8; ++j) {
                o[0][j] = fmaf(p0, vv[j], o[0][j]);
                o[1][j] = fmaf(p1, vv[j], o[1][j]);
                o[2][j] = fmaf(p2, vv[j], o[2][j]);
                o[3][j] = fmaf(p3, vv[j], o[3][j]);
            }
        }
    }

    float* Ah = A + headoff;
#pragma unroll
    for (int i = 0; i < 4; ++i) {
        const float inv = 1.f / l_i[i];
        const int row = qb * 64 + ty * 4 + i;
        float4 r0, r1;
        r0.x = tf32r(o[i][0] * inv); r0.y = tf32r(o[i][1] * inv);
        r0.z = tf32r(o[i][2] * inv); r0.w = tf32r(o[i][3] * inv);
        r1.x = tf32r(o[i][4] * inv); r1.y = tf32r(o[i][5] * inv);
        r1.z = tf32r(o[i][6] * inv); r1.w = tf32r(o[i][7] * inv);
        *(float4*)&Ah[(size_t)row * D_MODEL + tx * 8]     = r0;
        *(float4*)&Ah[(size_t)row * D_MODEL + tx * 8 + 4] = r1;
    }
}

// ---------------------------------------------------------------------------
extern "C" void kernel_launch(void* const* d_in, const int* in_sizes, int n_in,
                              void* d_out, int out_size)
{
    const float* xq = (const float*)d_in[0];
    const float* xk = (const float*)d_in[1];
    const float* xv = (const float*)d_in[2];
    const float* wq = (const float*)d_in[3];
    const float* wk = (const float*)d_in[4];
    const float* wv = (const float*)d_in[5];
    const float* wp = (const float*)d_in[6];
    const float* bp = (const float*)d_in[7];
    float* out = (float*)d_out;

    float *gq, *gk, *gv, *ga, *rxq, *rxk, *rxv, *rwq, *rwk, *rwv, *rwp;
    cudaGetSymbolAddress((void**)&gq,  g_q);
    cudaGetSymbolAddress((void**)&gk,  g_k);
    cudaGetSymbolAddress((void**)&gv,  g_v);
    cudaGetSymbolAddress((void**)&ga,  g_a);
    cudaGetSymbolAddress((void**)&rxq, g_rxq);
    cudaGetSymbolAddress((void**)&rxk, g_rxk);
    cudaGetSymbolAddress((void**)&rxv, g_rxv);
    cudaGetSymbolAddress((void**)&rwq, g_rwq);
    cudaGetSymbolAddress((void**)&rwk, g_rwk);
    cudaGetSymbolAddress((void**)&rwv, g_rwv);
    cudaGetSymbolAddress((void**)&rwp, g_rwp);

    cudaFuncSetAttribute(gemm_mma,
                         cudaFuncAttributeMaxDynamicSharedMemorySize, GEMM_SMEM);
    cudaFuncSetAttribute(flash_kernel,
                         cudaFuncAttributeMaxDynamicSharedMemorySize, FLASH_SMEM);

    const int nx4 = MROWS * D_MODEL / 4;
    const int nw4 = D_MODEL * D_MODEL / 4;
    round_tf32_kernel<<<nx4 / 256, 256>>>(xq, rxq, nx4);
    round_tf32_kernel<<<nx4 / 256, 256>>>(xk, rxk, nx4);
    round_tf32_kernel<<<nx4 / 256, 256>>>(xv, rxv, nx4);
    round_tf32_kernel<<<nw4 / 256, 256>>>(wq, rwq, nw4);
    round_tf32_kernel<<<nw4 / 256, 256>>>(wk, rwk, nw4);
    round_tf32_kernel<<<nw4 / 256, 256>>>(wv, rwv, nw4);
    round_tf32_kernel<<<nw4 / 256, 256>>>(wp, rwp, nw4);

    dim3 gg(D_MODEL / 128, MROWS / 128);     // (8, 64)
    gemm_mma<<<gg, 256, GEMM_SMEM>>>(rxq, rwq, nullptr, gq, 0);
    gemm_mma<<<gg, 256, GEMM_SMEM>>>(rxk, rwk, nullptr, gk, 0);
    gemm_mma<<<gg, 256, GEMM_SMEM>>>(rxv, rwv, nullptr, gv, 0);

    flash_kernel<<<dim3(SEQ / 64, BATCH * NH), 128, FLASH_SMEM>>>(gq, gk, gv, ga);

    gemm_mma<<<gg, 256, GEMM_SMEM>>>(ga, rwp, bp, out, 1);
}

// round 8
// speedup vs baseline: 2.6526x; 1.8555x over previous
#include <cuda_runtime.h>
#include <cuda_bf16.h>
#include <cstdint>
#include <math.h>

// Problem constants
#define D_MODEL 1024
#define DKH     64
#define NH      16
#define BATCH   4
#define SEQ     2048
#define MROWS   (BATCH * SEQ)   // 8192

// Scratch (device globals: allocation-free per harness rules)
__device__ float g_q[(size_t)MROWS * D_MODEL];
__device__ float g_k[(size_t)MROWS * D_MODEL];
__device__ float g_v[(size_t)MROWS * D_MODEL];
__device__ float g_a[(size_t)MROWS * D_MODEL];
// tf32-rounded GEMM inputs
__device__ float g_rxq[(size_t)MROWS * D_MODEL];
__device__ float g_rxk[(size_t)MROWS * D_MODEL];
__device__ float g_rxv[(size_t)MROWS * D_MODEL];
__device__ float g_rwq[(size_t)D_MODEL * D_MODEL];
__device__ float g_rwk[(size_t)D_MODEL * D_MODEL];
__device__ float g_rwv[(size_t)D_MODEL * D_MODEL];
__device__ float g_rwp[(size_t)D_MODEL * D_MODEL];

// ---------------------------------------------------------------------------
// Helpers (baseline PTX only — harness compiles at compute_103, which
// rejects tcgen05/'a'-features)
// ---------------------------------------------------------------------------
__device__ __forceinline__ uint32_t smem_u32(const void* p) {
    uint32_t a;
    asm("{ .reg .u64 t; cvta.to.shared.u64 t, %1; cvt.u32.u64 %0, t; }"
        : "=r"(a) : "l"(p));
    return a;
}
__device__ __forceinline__ float tf32r(float x) {
    uint32_t u;
    asm("cvt.rna.tf32.f32 %0, %1;" : "=r"(u) : "f"(x));
    return __uint_as_float(u);
}

#define CP_ASYNC16(dst, src) \
    asm volatile("cp.async.cg.shared.global [%0], [%1], 16;" :: "r"(dst), "l"(src))
#define CP_COMMIT() asm volatile("cp.async.commit_group;")
#define CP_WAIT(n)  asm volatile("cp.async.wait_group %0;" :: "n"(n))

// mma.sync m16n8k8 tf32: D = A*B + C (A row-major 16x8, B col-major 8x8)
// Frags: a0=(g,tig) a1=(g+8,tig) a2=(g,tig+4) a3=(g+8,tig+4);
//        b0=(k=tig,n=g) b1=(k=tig+4,n=g);
//        c0=(g,2tig) c1=(g,2tig+1) c2=(g+8,2tig) c3=(g+8,2tig+1)
#define MMA_TF32(c0, c1, c2, c3, a0, a1, a2, a3, b0, b1)                      \
    asm volatile(                                                             \
        "mma.sync.aligned.m16n8k8.row.col.f32.tf32.tf32.f32 "                 \
        "{%0,%1,%2,%3}, {%4,%5,%6,%7}, {%8,%9}, {%0,%1,%2,%3};"               \
        : "+f"(c0), "+f"(c1), "+f"(c2), "+f"(c3)                              \
        : "r"(a0), "r"(a1), "r"(a2), "r"(a3), "r"(b0), "r"(b1))

// ---------------------------------------------------------------------------
// tf32 pre-round pass
// ---------------------------------------------------------------------------
__global__ void round_tf32_kernel(const float* __restrict__ x,
                                  float* __restrict__ y, int n4)
{
    int i = blockIdx.x * blockDim.x + threadIdx.x;
    if (i < n4) {
        float4 v = ((const float4*)x)[i];
        v.x = tf32r(v.x); v.y = tf32r(v.y); v.z = tf32r(v.z); v.w = tf32r(v.w);
        ((float4*)y)[i] = v;
    }
}

// ---------------------------------------------------------------------------
// tf32 mma.sync GEMM: C[M,N] = X[M,K] * W[N,K]^T (+bias). M=8192, N=K=1024.
// roundOut: round outputs to tf32 (rna) so downstream mma consumers are unbiased.
// ---------------------------------------------------------------------------
#define BK      16
#define PITCH   20
#define ATILE   (128 * PITCH)
#define STAGEF  (2 * ATILE)
#define NSTAGE  4
#define GEMM_SMEM (NSTAGE * STAGEF * 4) // 81920 bytes
#define NCH     (D_MODEL / BK)          // 64 k-chunks

__global__ __launch_bounds__(256, 1)
void gemm_mma(const float* __restrict__ X, const float* __restrict__ W,
              const float* __restrict__ bias, float* __restrict__ C,
              int addBias, int roundOut)
{
    extern __shared__ float smf[];
    const int tid  = threadIdx.x;
    const int wid  = tid >> 5;
    const int lane = tid & 31;
    const int g    = lane >> 2;
    const int tig  = lane & 3;
    const int m0 = blockIdx.y * 128;
    const int n0 = blockIdx.x * 128;
    const int wm = (wid >> 2) * 64;
    const int wn = (wid & 3) * 32;

    float c[4][4][4];
#pragma unroll
    for (int mt = 0; mt < 4; ++mt)
#pragma unroll
        for (int nt = 0; nt < 4; ++nt)
#pragma unroll
            for (int r = 0; r < 4; ++r) c[mt][nt][r] = 0.f;

#define LOAD_STAGE(kt) do {                                                    \
        float* st = smf + ((kt) % NSTAGE) * STAGEF;                            \
        const int k0 = (kt) * BK;                                              \
        _Pragma("unroll")                                                      \
        for (int i = 0; i < 4; ++i) {                                          \
            const int idx  = i * 256 + tid;                                    \
            const int isB  = idx >> 9;                                         \
            const int row  = (idx >> 2) & 127;                                 \
            const int quad = idx & 3;                                          \
            float* dst = st + isB * ATILE + row * PITCH + quad * 4;            \
            const float* src = (isB ? W + (size_t)(n0 + row) * D_MODEL        \
                                    : X + (size_t)(m0 + row) * D_MODEL)       \
                               + k0 + quad * 4;                                \
            CP_ASYNC16(smem_u32(dst), src);                                    \
        }                                                                      \
        CP_COMMIT();                                                           \
    } while (0)

    LOAD_STAGE(0); LOAD_STAGE(1); LOAD_STAGE(2);

    for (int kt = 0; kt < NCH; ++kt) {
        if (kt < NCH - 2)       CP_WAIT(2);
        else if (kt == NCH - 2) CP_WAIT(1);
        else                    CP_WAIT(0);
        __syncthreads();

        if (kt + 3 < NCH) LOAD_STAGE(kt + 3);

        const float* As = smf + (kt % NSTAGE) * STAGEF;
        const float* Bs = As + ATILE;

#pragma unroll
        for (int ks = 0; ks < 2; ++ks) {
            const int kb = ks * 8;
            uint32_t a[4][4], b[4][2];
#pragma unroll
            for (int mt = 0; mt < 4; ++mt) {
                const float* ap = As + (wm + mt * 16 + g) * PITCH + kb + tig;
                a[mt][0] = __float_as_uint(ap[0]);
                a[mt][1] = __float_as_uint(ap[8 * PITCH]);
                a[mt][2] = __float_as_uint(ap[4]);
                a[mt][3] = __float_as_uint(ap[8 * PITCH + 4]);
            }
#pragma unroll
            for (int nt = 0; nt < 4; ++nt) {
                const float* bp = Bs + (wn + nt * 8 + g) * PITCH + kb + tig;
                b[nt][0] = __float_as_uint(bp[0]);
                b[nt][1] = __float_as_uint(bp[4]);
            }
#pragma unroll
            for (int mt = 0; mt < 4; ++mt)
#pragma unroll
                for (int nt = 0; nt < 4; ++nt)
                    MMA_TF32(c[mt][nt][0], c[mt][nt][1], c[mt][nt][2], c[mt][nt][3],
                             a[mt][0], a[mt][1], a[mt][2], a[mt][3],
                             b[nt][0], b[nt][1]);
        }
    }

#pragma unroll
    for (int mt = 0; mt < 4; ++mt) {
        const int row = m0 + wm + mt * 16 + g;
#pragma unroll
        for (int nt = 0; nt < 4; ++nt) {
            const int col = n0 + wn + nt * 8 + 2 * tig;
            float b0 = 0.f, b1 = 0.f;
            if (addBias) { b0 = bias[col]; b1 = bias[col + 1]; }
            float v0 = c[mt][nt][0] + b0, v1 = c[mt][nt][1] + b1;
            float v2 = c[mt][nt][2] + b0, v3 = c[mt][nt][3] + b1;
            if (roundOut) { v0 = tf32r(v0); v1 = tf32r(v1);
                            v2 = tf32r(v2); v3 = tf32r(v3); }
            *(float2*)&C[(size_t)row * D_MODEL + col]       = make_float2(v0, v1);
            *(float2*)&C[(size_t)(row + 8) * D_MODEL + col] = make_float2(v2, v3);
        }
    }
#undef LOAD_STAGE
}

// ---------------------------------------------------------------------------
// Causal flash attention with mma.sync tf32.
// BQ=128, BK=64, dk=64. 8 warps; warp w owns q-rows wm=w*16 .. +15.
// Q/K/V already tf32-rounded (gemm epilogue); P rounded at smem store.
// Smem pitch 68: A-frag loads conflict-free (banks 4g+tig distinct).
// ---------------------------------------------------------------------------
#define FP 68
#define FLASH_SMEM (384 * FP * 4)   // Qs 128 + Ks 64 + Vs 64 + Ps 128 rows

__global__ __launch_bounds__(256, 2)
void flash_mma(const float* __restrict__ Q, const float* __restrict__ K,
               const float* __restrict__ V, float* __restrict__ A)
{
    extern __shared__ float sm[];
    float* Qs = sm;                 // [128][FP]
    float* Ks = sm + 128 * FP;      // [64][FP]
    float* Vs = sm + 192 * FP;      // [64][FP]
    float* Ps = sm + 256 * FP;      // [128][FP]

    const int tid  = threadIdx.x;
    const int wid  = tid >> 5;
    const int lane = tid & 31;
    const int g    = lane >> 2;
    const int tig  = lane & 3;
    const int wm   = wid << 4;
    const int qb   = gridDim.x - 1 - blockIdx.x;   // heavy blocks first
    const int bh   = blockIdx.y;
    const int b    = bh >> 4, h = bh & 15;

    const size_t headoff = (size_t)b * SEQ * D_MODEL + (size_t)h * DKH;
    const float* Qh = Q + headoff;
    const float* Kh = K + headoff;
    const float* Vh = V + headoff;

    // Q tile: 128 x 64 fp32 via cp.async (2048 x 16B, 8 per thread)
#pragma unroll
    for (int i = 0; i < 8; ++i) {
        const int idx = i * 256 + tid;
        const int r   = idx >> 4;
        const int c4  = (idx & 15) << 2;
        CP_ASYNC16(smem_u32(Qs + r * FP + c4),
                   Qh + (size_t)(qb * 128 + r) * D_MODEL + c4);
    }
    CP_COMMIT();

    float oa[8][4];
#pragma unroll
    for (int nt = 0; nt < 8; ++nt)
#pragma unroll
        for (int r = 0; r < 4; ++r) oa[nt][r] = 0.f;
    float mr0 = -1e30f, mr1 = -1e30f, lr0 = 0.f, lr1 = 0.f;

    const int ntile = 2 * qb + 2;
    const int qrow0 = qb * 128 + wm + g;   // within-sequence index
    const int qrow1 = qrow0 + 8;

    for (int t = 0; t < ntile; ++t) {
        __syncthreads();    // all warps done with Ks/Vs of previous tile
#pragma unroll
        for (int i = 0; i < 8; ++i) {
            const int idx = i * 256 + tid;
            const int isV = idx >> 10;
            const int r   = (idx >> 4) & 63;
            const int c4  = (idx & 15) << 2;
            const float* src = (isV ? Vh : Kh) + (size_t)(t * 64 + r) * D_MODEL + c4;
            float* dst = (isV ? Vs : Ks) + r * FP + c4;
            CP_ASYNC16(smem_u32(dst), src);
        }
        CP_COMMIT();
        CP_WAIT(0);         // first iter also covers the Q tile
        __syncthreads();

        // ---- S = Q K^T (warp rows wm..wm+15, tile cols 0..63) ----
        float sacc[8][4];
#pragma unroll
        for (int nt = 0; nt < 8; ++nt)
#pragma unroll
            for (int r = 0; r < 4; ++r) sacc[nt][r] = 0.f;

#pragma unroll
        for (int ks = 0; ks < 8; ++ks) {
            const float* ap = Qs + (wm + g) * FP + ks * 8 + tig;
            const uint32_t a0 = __float_as_uint(ap[0]);
            const uint32_t a1 = __float_as_uint(ap[8 * FP]);
            const uint32_t a2 = __float_as_uint(ap[4]);
            const uint32_t a3 = __float_as_uint(ap[8 * FP + 4]);
#pragma unroll
            for (int nt = 0; nt < 8; ++nt) {
                const float* bp = Ks + (nt * 8 + g) * FP + ks * 8 + tig;
                const uint32_t b0 = __float_as_uint(bp[0]);
                const uint32_t b1 = __float_as_uint(bp[4]);
                MMA_TF32(sacc[nt][0], sacc[nt][1], sacc[nt][2], sacc[nt][3],
                         a0, a1, a2, a3, b0, b1);
            }
        }

        // ---- scale + causal mask (last two tiles only) ----
        const bool tail = (t >= 2 * qb);
        const int cb = t * 64 + 2 * tig;
        float mx0 = -1e30f, mx1 = -1e30f;
#pragma unroll
        for (int nt = 0; nt < 8; ++nt) {
            const int c0 = cb + nt * 8, c1 = c0 + 1;
            float v0 = sacc[nt][0] * 0.125f;
            float v1 = sacc[nt][1] * 0.125f;
            float v2 = sacc[nt][2] * 0.125f;
            float v3 = sacc[nt][3] * 0.125f;
            if (tail) {
                if (c0 > qrow0) v0 = -1e30f;
                if (c1 > qrow0) v1 = -1e30f;
                if (c0 > qrow1) v2 = -1e30f;
                if (c1 > qrow1) v3 = -1e30f;
            }
            sacc[nt][0] = v0; sacc[nt][1] = v1;
            sacc[nt][2] = v2; sacc[nt][3] = v3;
            mx0 = fmaxf(mx0, fmaxf(v0, v1));
            mx1 = fmaxf(mx1, fmaxf(v2, v3));
        }
        // row reductions: only across the 4 tig lanes (intra-warp)
        mx0 = fmaxf(mx0, __shfl_xor_sync(0xffffffffu, mx0, 1));
        mx0 = fmaxf(mx0, __shfl_xor_sync(0xffffffffu, mx0, 2));
        mx1 = fmaxf(mx1, __shfl_xor_sync(0xffffffffu, mx1, 1));
        mx1 = fmaxf(mx1, __shfl_xor_sync(0xffffffffu, mx1, 2));

        const float mn0 = fmaxf(mr0, mx0);
        const float mn1 = fmaxf(mr1, mx1);
        const float co0 = __expf(mr0 - mn0);
        const float co1 = __expf(mr1 - mn1);
        mr0 = mn0; mr1 = mn1;

        float rs0 = 0.f, rs1 = 0.f;
        float* pr0 = Ps + (wm + g) * FP + 2 * tig;
        float* pr1 = pr0 + 8 * FP;
#pragma unroll
        for (int nt = 0; nt < 8; ++nt) {
            const float p0 = __expf(sacc[nt][0] - mn0);
            const float p1 = __expf(sacc[nt][1] - mn0);
            const float p2 = __expf(sacc[nt][2] - mn1);
            const float p3 = __expf(sacc[nt][3] - mn1);
            rs0 += p0 + p1; rs1 += p2 + p3;
            *(float2*)(pr0 + nt * 8) = make_float2(tf32r(p0), tf32r(p1));
            *(float2*)(pr1 + nt * 8) = make_float2(tf32r(p2), tf32r(p3));
        }
        rs0 += __shfl_xor_sync(0xffffffffu, rs0, 1);
        rs0 += __shfl_xor_sync(0xffffffffu, rs0, 2);
        rs1 += __shfl_xor_sync(0xffffffffu, rs1, 1);
        rs1 += __shfl_xor_sync(0xffffffffu, rs1, 2);
        lr0 = lr0 * co0 + rs0;
        lr1 = lr1 * co1 + rs1;

#pragma unroll
        for (int nt = 0; nt < 8; ++nt) {
            oa[nt][0] *= co0; oa[nt][1] *= co0;
            oa[nt][2] *= co1; oa[nt][3] *= co1;
        }
        __syncwarp();   // P stores visible to the warp (only own warp reads)

        // ---- O += P V ----
#pragma unroll
        for (int ks = 0; ks < 8; ++ks) {
            const float* ap = Ps + (wm + g) * FP + ks * 8 + tig;
            const uint32_t a0 = __float_as_uint(ap[0]);
            const uint32_t a1 = __float_as_uint(ap[8 * FP]);
            const uint32_t a2 = __float_as_uint(ap[4]);
            const uint32_t a3 = __float_as_uint(ap[8 * FP + 4]);
#pragma unroll
            for (int nt = 0; nt < 8; ++nt) {
                const float* bp = Vs + (ks * 8 + tig) * FP + nt * 8 + g;
                const uint32_t b0 = __float_as_uint(bp[0]);
                const uint32_t b1 = __float_as_uint(bp[4 * FP]);
                MMA_TF32(oa[nt][0], oa[nt][1], oa[nt][2], oa[nt][3],
                         a0, a1, a2, a3, b0, b1);
            }
        }
    }

    // ---- epilogue: normalize + tf32-round (final GEMM consumes this) ----
    const float inv0 = 1.f / lr0;
    const float inv1 = 1.f / lr1;
    float* Ar0 = (float*)(A + headoff + (size_t)qrow0 * D_MODEL);
    float* Ar1 = (float*)(A + headoff + (size_t)qrow1 * D_MODEL);
#pragma unroll
    for (int nt = 0; nt < 8; ++nt) {
        const int col = nt * 8 + 2 * tig;
        *(float2*)(Ar0 + col) = make_float2(tf32r(oa[nt][0] * inv0),
                                            tf32r(oa[nt][1] * inv0));
        *(float2*)(Ar1 + col) = make_float2(tf32r(oa[nt][2] * inv1),
                                            tf32r(oa[nt][3] * inv1));
    }
}

// ---------------------------------------------------------------------------
extern "C" void kernel_launch(void* const* d_in, const int* in_sizes, int n_in,
                              void* d_out, int out_size)
{
    const float* xq = (const float*)d_in[0];
    const float* xk = (const float*)d_in[1];
    const float* xv = (const float*)d_in[2];
    const float* wq = (const float*)d_in[3];
    const float* wk = (const float*)d_in[4];
    const float* wv = (const float*)d_in[5];
    const float* wp = (const float*)d_in[6];
    const float* bp = (const float*)d_in[7];
    float* out = (float*)d_out;

    float *gq, *gk, *gv, *ga, *rxq, *rxk, *rxv, *rwq, *rwk, *rwv, *rwp;
    cudaGetSymbolAddress((void**)&gq,  g_q);
    cudaGetSymbolAddress((void**)&gk,  g_k);
    cudaGetSymbolAddress((void**)&gv,  g_v);
    cudaGetSymbolAddress((void**)&ga,  g_a);
    cudaGetSymbolAddress((void**)&rxq, g_rxq);
    cudaGetSymbolAddress((void**)&rxk, g_rxk);
    cudaGetSymbolAddress((void**)&rxv, g_rxv);
    cudaGetSymbolAddress((void**)&rwq, g_rwq);
    cudaGetSymbolAddress((void**)&rwk, g_rwk);
    cudaGetSymbolAddress((void**)&rwv, g_rwv);
    cudaGetSymbolAddress((void**)&rwp, g_rwp);

    cudaFuncSetAttribute(gemm_mma,
                         cudaFuncAttributeMaxDynamicSharedMemorySize, GEMM_SMEM);
    cudaFuncSetAttribute(flash_mma,
                         cudaFuncAttributeMaxDynamicSharedMemorySize, FLASH_SMEM);

    const int nx4 = MROWS * D_MODEL / 4;
    const int nw4 = D_MODEL * D_MODEL / 4;
    round_tf32_kernel<<<nx4 / 256, 256>>>(xq, rxq, nx4);
    round_tf32_kernel<<<nx4 / 256, 256>>>(xk, rxk, nx4);
    round_tf32_kernel<<<nx4 / 256, 256>>>(xv, rxv, nx4);
    round_tf32_kernel<<<nw4 / 256, 256>>>(wq, rwq, nw4);
    round_tf32_kernel<<<nw4 / 256, 256>>>(wk, rwk, nw4);
    round_tf32_kernel<<<nw4 / 256, 256>>>(wv, rwv, nw4);
    round_tf32_kernel<<<nw4 / 256, 256>>>(wp, rwp, nw4);

    dim3 gg(D_MODEL / 128, MROWS / 128);     // (8, 64)
    // Q/K/V projections: round outputs to tf32 (flash consumes them in mma)
    gemm_mma<<<gg, 256, GEMM_SMEM>>>(rxq, rwq, nullptr, gq, 0, 1);
    gemm_mma<<<gg, 256, GEMM_SMEM>>>(rxk, rwk, nullptr, gk, 0, 1);
    gemm_mma<<<gg, 256, GEMM_SMEM>>>(rxv, rwv, nullptr, gv, 0, 1);

    flash_mma<<<dim3(SEQ / 128, BATCH * NH), 256, FLASH_SMEM>>>(gq, gk, gv, ga);

    // Output projection: full fp32 out
    gemm_mma<<<gg, 256, GEMM_SMEM>>>(ga, rwp, bp, out, 1, 0);
}

// round 11
// speedup vs baseline: 3.0164x; 1.1371x over previous
#include <cuda_runtime.h>
#include <cuda_bf16.h>
#include <cstdint>
#include <math.h>

// Problem constants
#define D_MODEL 1024
#define DKH     64
#define NH      16
#define BATCH   4
#define SEQ     2048
#define MROWS   (BATCH * SEQ)   // 8192

// Scratch (device globals: allocation-free per harness rules)
__device__ float g_q[(size_t)MROWS * D_MODEL];
__device__ float g_k[(size_t)MROWS * D_MODEL];
__device__ float g_v[(size_t)MROWS * D_MODEL];
__device__ float g_a[(size_t)MROWS * D_MODEL];
// tf32-rounded GEMM inputs
__device__ float g_rxq[(size_t)MROWS * D_MODEL];
__device__ float g_rxk[(size_t)MROWS * D_MODEL];
__device__ float g_rxv[(size_t)MROWS * D_MODEL];
__device__ float g_rwq[(size_t)D_MODEL * D_MODEL];
__device__ float g_rwk[(size_t)D_MODEL * D_MODEL];
__device__ float g_rwv[(size_t)D_MODEL * D_MODEL];
__device__ float g_rwp[(size_t)D_MODEL * D_MODEL];

// ---------------------------------------------------------------------------
// Helpers (baseline PTX only — harness compiles at compute_103, which
// rejects tcgen05/'a'-features)
// ---------------------------------------------------------------------------
__device__ __forceinline__ uint32_t smem_u32(const void* p) {
    uint32_t a;
    asm("{ .reg .u64 t; cvta.to.shared.u64 t, %1; cvt.u32.u64 %0, t; }"
        : "=r"(a) : "l"(p));
    return a;
}
__device__ __forceinline__ float tf32r(float x) {
    uint32_t u;
    asm("cvt.rna.tf32.f32 %0, %1;" : "=r"(u) : "f"(x));
    return __uint_as_float(u);
}

#define CP_ASYNC16(dst, src) \
    asm volatile("cp.async.cg.shared.global [%0], [%1], 16;" :: "r"(dst), "l"(src))
#define CP_COMMIT() asm volatile("cp.async.commit_group;")
#define CP_WAIT(n)  asm volatile("cp.async.wait_group %0;" :: "n"(n))

// mma.sync m16n8k8 tf32: D = A*B + C (A row-major 16x8, B col-major 8x8)
#define MMA_TF32(c0, c1, c2, c3, a0, a1, a2, a3, b0, b1)                      \
    asm volatile(                                                             \
        "mma.sync.aligned.m16n8k8.row.col.f32.tf32.tf32.f32 "                 \
        "{%0,%1,%2,%3}, {%4,%5,%6,%7}, {%8,%9}, {%0,%1,%2,%3};"               \
        : "+f"(c0), "+f"(c1), "+f"(c2), "+f"(c3)                              \
        : "r"(a0), "r"(a1), "r"(a2), "r"(a3), "r"(b0), "r"(b1))

// ---------------------------------------------------------------------------
// Fused tf32 pre-round pass: one launch for all 7 arrays (grid.y selects)
// ---------------------------------------------------------------------------
struct RoundArgs {
    const float* src[7];
    float*       dst[7];
    int          n4[7];
};

__global__ void round_all_kernel(RoundArgs p)
{
    const int y = blockIdx.y;
    const int i = blockIdx.x * blockDim.x + threadIdx.x;
    if (i < p.n4[y]) {
        float4 v = ((const float4*)p.src[y])[i];
        v.x = tf32r(v.x); v.y = tf32r(v.y); v.z = tf32r(v.z); v.w = tf32r(v.w);
        ((float4*)p.dst[y])[i] = v;
    }
}

// ---------------------------------------------------------------------------
// tf32 mma.sync GEMM: C[M,N] = X[M,K] * W[N,K]^T (+bias). M=8192, N=K=1024.
// 128x128 CTA tile, 8 warps 64x32, BK=16, 4-stage cp.async, occupancy 2.
// ---------------------------------------------------------------------------
#define BK      16
#define PITCH   20
#define ATILE   (128 * PITCH)
#define STAGEF  (2 * ATILE)
#define NSTAGE  4
#define GEMM_SMEM (NSTAGE * STAGEF * 4) // 81920 bytes (x2 CTAs = 160KB < 228KB)
#define NCH     (D_MODEL / BK)          // 64 k-chunks

__global__ __launch_bounds__(256, 2)
void gemm_mma(const float* __restrict__ X, const float* __restrict__ W,
              const float* __restrict__ bias, float* __restrict__ C,
              int addBias, int roundOut)
{
    extern __shared__ float smf[];
    const int tid  = threadIdx.x;
    const int wid  = tid >> 5;
    const int lane = tid & 31;
    const int g    = lane >> 2;
    const int tig  = lane & 3;
    const int m0 = blockIdx.y * 128;
    const int n0 = blockIdx.x * 128;
    const int wm = (wid >> 2) * 64;
    const int wn = (wid & 3) * 32;

    float c[4][4][4];
#pragma unroll
    for (int mt = 0; mt < 4; ++mt)
#pragma unroll
        for (int nt = 0; nt < 4; ++nt)
#pragma unroll
            for (int r = 0; r < 4; ++r) c[mt][nt][r] = 0.f;

#define LOAD_STAGE(kt) do {                                                    \
        float* st = smf + ((kt) % NSTAGE) * STAGEF;                            \
        const int k0 = (kt) * BK;                                              \
        _Pragma("unroll")                                                      \
        for (int i = 0; i < 4; ++i) {                                          \
            const int idx  = i * 256 + tid;                                    \
            const int isB  = idx >> 9;                                         \
            const int row  = (idx >> 2) & 127;                                 \
            const int quad = idx & 3;                                          \
            float* dst = st + isB * ATILE + row * PITCH + quad * 4;            \
            const float* src = (isB ? W + (size_t)(n0 + row) * D_MODEL        \
                                    : X + (size_t)(m0 + row) * D_MODEL)       \
                               + k0 + quad * 4;                                \
            CP_ASYNC16(smem_u32(dst), src);                                    \
        }                                                                      \
        CP_COMMIT();                                                           \
    } while (0)

    LOAD_STAGE(0); LOAD_STAGE(1); LOAD_STAGE(2);

    for (int kt = 0; kt < NCH; ++kt) {
        if (kt < NCH - 2)       CP_WAIT(2);
        else if (kt == NCH - 2) CP_WAIT(1);
        else                    CP_WAIT(0);
        __syncthreads();

        if (kt + 3 < NCH) LOAD_STAGE(kt + 3);

        const float* As = smf + (kt % NSTAGE) * STAGEF;
        const float* Bs = As + ATILE;

#pragma unroll
        for (int ks = 0; ks < 2; ++ks) {
            const int kb = ks * 8;
            uint32_t a[4][4], b[4][2];
#pragma unroll
            for (int mt = 0; mt < 4; ++mt) {
                const float* ap = As + (wm + mt * 16 + g) * PITCH + kb + tig;
                a[mt][0] = __float_as_uint(ap[0]);
                a[mt][1] = __float_as_uint(ap[8 * PITCH]);
                a[mt][2] = __float_as_uint(ap[4]);
                a[mt][3] = __float_as_uint(ap[8 * PITCH + 4]);
            }
#pragma unroll
            for (int nt = 0; nt < 4; ++nt) {
                const float* bp = Bs + (wn + nt * 8 + g) * PITCH + kb + tig;
                b[nt][0] = __float_as_uint(bp[0]);
                b[nt][1] = __float_as_uint(bp[4]);
            }
#pragma unroll
            for (int mt = 0; mt < 4; ++mt)
#pragma unroll
                for (int nt = 0; nt < 4; ++nt)
                    MMA_TF32(c[mt][nt][0], c[mt][nt][1], c[mt][nt][2], c[mt][nt][3],
                             a[mt][0], a[mt][1], a[mt][2], a[mt][3],
                             b[nt][0], b[nt][1]);
        }
    }

#pragma unroll
    for (int mt = 0; mt < 4; ++mt) {
        const int row = m0 + wm + mt * 16 + g;
#pragma unroll
        for (int nt = 0; nt < 4; ++nt) {
            const int col = n0 + wn + nt * 8 + 2 * tig;
            float b0 = 0.f, b1 = 0.f;
            if (addBias) { b0 = bias[col]; b1 = bias[col + 1]; }
            float v0 = c[mt][nt][0] + b0, v1 = c[mt][nt][1] + b1;
            float v2 = c[mt][nt][2] + b0, v3 = c[mt][nt][3] + b1;
            if (roundOut) { v0 = tf32r(v0); v1 = tf32r(v1);
                            v2 = tf32r(v2); v3 = tf32r(v3); }
            *(float2*)&C[(size_t)row * D_MODEL + col]       = make_float2(v0, v1);
            *(float2*)&C[(size_t)(row + 8) * D_MODEL + col] = make_float2(v2, v3);
        }
    }
#undef LOAD_STAGE
}

// ---------------------------------------------------------------------------
// Causal flash attention with mma.sync tf32 + software-pipelined K/V loads.
// BQ=128, BK=64. Schedule per tile t (single-buffered Ks/Vs, full overlap):
//   wait K(t); bar; issue V(t); S-mma + softmax (V loads in flight);
//   bar; issue K(t+1); wait V(t); bar; PV (K(t+1) loads in flight)
// ---------------------------------------------------------------------------
#define FP 68
#define FLASH_SMEM (384 * FP * 4)   // Qs 128 + Ks 64 + Vs 64 + Ps 128 rows

__global__ __launch_bounds__(256, 2)
void flash_mma(const float* __restrict__ Q, const float* __restrict__ K,
               const float* __restrict__ V, float* __restrict__ A)
{
    extern __shared__ float sm[];
    float* Qs = sm;                 // [128][FP]
    float* Ks = sm + 128 * FP;      // [64][FP]
    float* Vs = sm + 192 * FP;      // [64][FP]
    float* Ps = sm + 256 * FP;      // [128][FP]

    const int tid  = threadIdx.x;
    const int wid  = tid >> 5;
    const int lane = tid & 31;
    const int g    = lane >> 2;
    const int tig  = lane & 3;
    const int wm   = wid << 4;
    const int qb   = gridDim.x - 1 - blockIdx.x;   // heavy blocks first
    const int bh   = blockIdx.y;
    const int b    = bh >> 4, h = bh & 15;

    const size_t headoff = (size_t)b * SEQ * D_MODEL + (size_t)h * DKH;
    const float* Qh = Q + headoff;
    const float* Kh = K + headoff;
    const float* Vh = V + headoff;

    const int ntile = 2 * qb + 2;
    const int qrow0 = qb * 128 + wm + g;
    const int qrow1 = qrow0 + 8;

    // Preload: Q tile (8 x 16B per thread) + K(0) (4 x 16B) in ONE group.
#pragma unroll
    for (int i = 0; i < 8; ++i) {
        const int idx = i * 256 + tid;
        const int r   = idx >> 4;
        const int c4  = (idx & 15) << 2;
        CP_ASYNC16(smem_u32(Qs + r * FP + c4),
                   Qh + (size_t)(qb * 128 + r) * D_MODEL + c4);
    }
#pragma unroll
    for (int i = 0; i < 4; ++i) {
        const int idx = i * 256 + tid;
        const int r   = idx >> 4;
        const int c4  = (idx & 15) << 2;
        CP_ASYNC16(smem_u32(Ks + r * FP + c4),
                   Kh + (size_t)r * D_MODEL + c4);
    }
    CP_COMMIT();

    float oa[8][4];
#pragma unroll
    for (int nt = 0; nt < 8; ++nt)
#pragma unroll
        for (int r = 0; r < 4; ++r) oa[nt][r] = 0.f;
    float mr0 = -1e30f, mr1 = -1e30f, lr0 = 0.f, lr1 = 0.f;

    for (int t = 0; t < ntile; ++t) {
        CP_WAIT(0);         // K(t) (and Q on t=0) done (this thread's copies)
        __syncthreads();    // global visibility; prev PV done -> Vs writable

        // issue V(t) — overlaps with S-mma + softmax below
#pragma unroll
        for (int i = 0; i < 4; ++i) {
            const int idx = i * 256 + tid;
            const int r   = idx >> 4;
            const int c4  = (idx & 15) << 2;
            CP_ASYNC16(smem_u32(Vs + r * FP + c4),
                       Vh + (size_t)(t * 64 + r) * D_MODEL + c4);
        }
        CP_COMMIT();

        // ---- S = Q K^T ----
        float sacc[8][4];
#pragma unroll
        for (int nt = 0; nt < 8; ++nt)
#pragma unroll
            for (int r = 0; r < 4; ++r) sacc[nt][r] = 0.f;

#pragma unroll
        for (int ks = 0; ks < 8; ++ks) {
            const float* ap = Qs + (wm + g) * FP + ks * 8 + tig;
            const uint32_t a0 = __float_as_uint(ap[0]);
            const uint32_t a1 = __float_as_uint(ap[8 * FP]);
            const uint32_t a2 = __float_as_uint(ap[4]);
            const uint32_t a3 = __float_as_uint(ap[8 * FP + 4]);
#pragma unroll
            for (int nt = 0; nt < 8; ++nt) {
                const float* bp = Ks + (nt * 8 + g) * FP + ks * 8 + tig;
                const uint32_t b0 = __float_as_uint(bp[0]);
                const uint32_t b1 = __float_as_uint(bp[4]);
                MMA_TF32(sacc[nt][0], sacc[nt][1], sacc[nt][2], sacc[nt][3],
                         a0, a1, a2, a3, b0, b1);
            }
        }

        // ---- scale + causal mask (last two tiles only) ----
        const bool tail = (t >= 2 * qb);
        const int cb = t * 64 + 2 * tig;
        float mx0 = -1e30f, mx1 = -1e30f;
#pragma unroll
        for (int nt = 0; nt < 8; ++nt) {
            const int c0 = cb + nt * 8, c1 = c0 + 1;
            float v0 = sacc[nt][0] * 0.125f;
            float v1 = sacc[nt][1] * 0.125f;
            float v2 = sacc[nt][2] * 0.125f;
            float v3 = sacc[nt][3] * 0.125f;
            if (tail) {
                if (c0 > qrow0) v0 = -1e30f;
                if (c1 > qrow0) v1 = -1e30f;
                if (c0 > qrow1) v2 = -1e30f;
                if (c1 > qrow1) v3 = -1e30f;
            }
            sacc[nt][0] = v0; sacc[nt][1] = v1;
            sacc[nt][2] = v2; sacc[nt][3] = v3;
            mx0 = fmaxf(mx0, fmaxf(v0, v1));
            mx1 = fmaxf(mx1, fmaxf(v2, v3));
        }
        mx0 = fmaxf(mx0, __shfl_xor_sync(0xffffffffu, mx0, 1));
        mx0 = fmaxf(mx0, __shfl_xor_sync(0xffffffffu, mx0, 2));
        mx1 = fmaxf(mx1, __shfl_xor_sync(0xffffffffu, mx1, 1));
        mx1 = fmaxf(mx1, __shfl_xor_sync(0xffffffffu, mx1, 2));

        const float mn0 = fmaxf(mr0, mx0);
        const float mn1 = fmaxf(mr1, mx1);
        const float co0 = __expf(mr0 - mn0);
        const float co1 = __expf(mr1 - mn1);
        mr0 = mn0; mr1 = mn1;

        float rs0 = 0.f, rs1 = 0.f;
        float* pr0 = Ps + (wm + g) * FP + 2 * tig;
        float* pr1 = pr0 + 8 * FP;
#pragma unroll
        for (int nt = 0; nt < 8; ++nt) {
            const float p0 = __expf(sacc[nt][0] - mn0);
            const float p1 = __expf(sacc[nt][1] - mn0);
            const float p2 = __expf(sacc[nt][2] - mn1);
            const float p3 = __expf(sacc[nt][3] - mn1);
            rs0 += p0 + p1; rs1 += p2 + p3;
            *(float2*)(pr0 + nt * 8) = make_float2(tf32r(p0), tf32r(p1));
            *(float2*)(pr1 + nt * 8) = make_float2(tf32r(p2), tf32r(p3));
        }
        rs0 += __shfl_xor_sync(0xffffffffu, rs0, 1);
        rs0 += __shfl_xor_sync(0xffffffffu, rs0, 2);
        rs1 += __shfl_xor_sync(0xffffffffu, rs1, 1);
        rs1 += __shfl_xor_sync(0xffffffffu, rs1, 2);
        lr0 = lr0 * co0 + rs0;
        lr1 = lr1 * co1 + rs1;

#pragma unroll
        for (int nt = 0; nt < 8; ++nt) {
            oa[nt][0] *= co0; oa[nt][1] *= co0;
            oa[nt][2] *= co1; oa[nt][3] *= co1;
        }
        __syncwarp();       // P stores visible to own warp

        __syncthreads();    // all warps done reading Ks -> Ks writable

        // issue K(t+1) — overlaps with PV below
        if (t + 1 < ntile) {
#pragma unroll
            for (int i = 0; i < 4; ++i) {
                const int idx = i * 256 + tid;
                const int r   = idx >> 4;
                const int c4  = (idx & 15) << 2;
                CP_ASYNC16(smem_u32(Ks + r * FP + c4),
                           Kh + (size_t)((t + 1) * 64 + r) * D_MODEL + c4);
            }
            CP_COMMIT();
            CP_WAIT(1);     // V(t) done (K(t+1) still in flight)
        } else {
            CP_WAIT(0);     // V(t) done
        }
        __syncthreads();    // V globally visible

        // ---- O += P V ----
#pragma unroll
        for (int ks = 0; ks < 8; ++ks) {
            const float* ap = Ps + (wm + g) * FP + ks * 8 + tig;
            const uint32_t a0 = __float_as_uint(ap[0]);
            const uint32_t a1 = __float_as_uint(ap[8 * FP]);
            const uint32_t a2 = __float_as_uint(ap[4]);
            const uint32_t a3 = __float_as_uint(ap[8 * FP + 4]);
#pragma unroll
            for (int nt = 0; nt < 8; ++nt) {
                const float* bp = Vs + (ks * 8 + tig) * FP + nt * 8 + g;
                const uint32_t b0 = __float_as_uint(bp[0]);
                const uint32_t b1 = __float_as_uint(bp[4 * FP]);
                MMA_TF32(oa[nt][0], oa[nt][1], oa[nt][2], oa[nt][3],
                         a0, a1, a2, a3, b0, b1);
            }
        }
    }

    // ---- epilogue: normalize + tf32-round (final GEMM consumes this) ----
    const float inv0 = 1.f / lr0;
    const float inv1 = 1.f / lr1;
    float* Ar0 = (float*)(A + headoff + (size_t)qrow0 * D_MODEL);
    float* Ar1 = (float*)(A + headoff + (size_t)qrow1 * D_MODEL);
#pragma unroll
    for (int nt = 0; nt < 8; ++nt) {
        const int col = nt * 8 + 2 * tig;
        *(float2*)(Ar0 + col) = make_float2(tf32r(oa[nt][0] * inv0),
                                            tf32r(oa[nt][1] * inv0));
        *(float2*)(Ar1 + col) = make_float2(tf32r(oa[nt][2] * inv1),
                                            tf32r(oa[nt][3] * inv1));
    }
}

// ---------------------------------------------------------------------------
extern "C" void kernel_launch(void* const* d_in, const int* in_sizes, int n_in,
                              void* d_out, int out_size)
{
    const float* xq = (const float*)d_in[0];
    const float* xk = (const float*)d_in[1];
    const float* xv = (const float*)d_in[2];
    const float* wq = (const float*)d_in[3];
    const float* wk = (const float*)d_in[4];
    const float* wv = (const float*)d_in[5];
    const float* wp = (const float*)d_in[6];
    const float* bp = (const float*)d_in[7];
    float* out = (float*)d_out;

    float *gq, *gk, *gv, *ga, *rxq, *rxk, *rxv, *rwq, *rwk, *rwv, *rwp;
    cudaGetSymbolAddress((void**)&gq,  g_q);
    cudaGetSymbolAddress((void**)&gk,  g_k);
    cudaGetSymbolAddress((void**)&gv,  g_v);
    cudaGetSymbolAddress((void**)&ga,  g_a);
    cudaGetSymbolAddress((void**)&rxq, g_rxq);
    cudaGetSymbolAddress((void**)&rxk, g_rxk);
    cudaGetSymbolAddress((void**)&rxv, g_rxv);
    cudaGetSymbolAddress((void**)&rwq, g_rwq);
    cudaGetSymbolAddress((void**)&rwk, g_rwk);
    cudaGetSymbolAddress((void**)&rwv, g_rwv);
    cudaGetSymbolAddress((void**)&rwp, g_rwp);

    cudaFuncSetAttribute(gemm_mma,
                         cudaFuncAttributeMaxDynamicSharedMemorySize, GEMM_SMEM);
    cudaFuncSetAttribute(flash_mma,
                         cudaFuncAttributeMaxDynamicSharedMemorySize, FLASH_SMEM);

    const int nx4 = MROWS * D_MODEL / 4;     // 2097152
    const int nw4 = D_MODEL * D_MODEL / 4;   // 262144

    RoundArgs ra;
    ra.src[0] = xq; ra.dst[0] = rxq; ra.n4[0] = nx4;
    ra.src[1] = xk; ra.dst[1] = rxk; ra.n4[1] = nx4;
    ra.src[2] = xv; ra.dst[2] = rxv; ra.n4[2] = nx4;
    ra.src[3] = wq; ra.dst[3] = rwq; ra.n4[3] = nw4;
    ra.src[4] = wk; ra.dst[4] = rwk; ra.n4[4] = nw4;
    ra.src[5] = wv; ra.dst[5] = rwv; ra.n4[5] = nw4;
    ra.src[6] = wp; ra.dst[6] = rwp; ra.n4[6] = nw4;
    round_all_kernel<<<dim3(nx4 / 256, 7), 256>>>(ra);

    dim3 gg(D_MODEL / 128, MROWS / 128);     // (8, 64)
    gemm_mma<<<gg, 256, GEMM_SMEM>>>(rxq, rwq, nullptr, gq, 0, 1);
    gemm_mma<<<gg, 256, GEMM_SMEM>>>(rxk, rwk, nullptr, gk, 0, 1);
    gemm_mma<<<gg, 256, GEMM_SMEM>>>(rxv, rwv, nullptr, gv, 0, 1);

    flash_mma<<<dim3(SEQ / 128, BATCH * NH), 256, FLASH_SMEM>>>(gq, gk, gv, ga);

    gemm_mma<<<gg, 256, GEMM_SMEM>>>(ga, rwp, bp, out, 1, 0);
}

// round 12
// speedup vs baseline: 3.0379x; 1.0071x over previous
#include <cuda_runtime.h>
#include <cuda_bf16.h>
#include <cstdint>
#include <math.h>

// Problem constants
#define D_MODEL 1024
#define DKH     64
#define NH      16
#define BATCH   4
#define SEQ     2048
#define MROWS   (BATCH * SEQ)   // 8192

// Scratch (device globals: allocation-free per harness rules)
__device__ float g_q[(size_t)MROWS * D_MODEL];
__device__ float g_k[(size_t)MROWS * D_MODEL];
__device__ float g_v[(size_t)MROWS * D_MODEL];
__device__ float g_a[(size_t)MROWS * D_MODEL];
// tf32-rounded GEMM inputs
__device__ float g_rxq[(size_t)MROWS * D_MODEL];
__device__ float g_rxk[(size_t)MROWS * D_MODEL];
__device__ float g_rxv[(size_t)MROWS * D_MODEL];
__device__ float g_rwq[(size_t)D_MODEL * D_MODEL];
__device__ float g_rwk[(size_t)D_MODEL * D_MODEL];
__device__ float g_rwv[(size_t)D_MODEL * D_MODEL];
__device__ float g_rwp[(size_t)D_MODEL * D_MODEL];

// ---------------------------------------------------------------------------
// Helpers (baseline PTX only — harness compiles at compute_103)
// ---------------------------------------------------------------------------
__device__ __forceinline__ uint32_t smem_u32(const void* p) {
    uint32_t a;
    asm("{ .reg .u64 t; cvta.to.shared.u64 t, %1; cvt.u32.u64 %0, t; }"
        : "=r"(a) : "l"(p));
    return a;
}
__device__ __forceinline__ float tf32r(float x) {
    uint32_t u;
    asm("cvt.rna.tf32.f32 %0, %1;" : "=r"(u) : "f"(x));
    return __uint_as_float(u);
}

#define CP_ASYNC16(dst, src) \
    asm volatile("cp.async.cg.shared.global [%0], [%1], 16;" :: "r"(dst), "l"(src))
#define CP_COMMIT() asm volatile("cp.async.commit_group;")
#define CP_WAIT(n)  asm volatile("cp.async.wait_group %0;" :: "n"(n))

// mma.sync m16n8k8 tf32: D = A*B + C (A row-major 16x8, B col-major 8x8)
#define MMA_TF32(c0, c1, c2, c3, a0, a1, a2, a3, b0, b1)                      \
    asm volatile(                                                             \
        "mma.sync.aligned.m16n8k8.row.col.f32.tf32.tf32.f32 "                 \
        "{%0,%1,%2,%3}, {%4,%5,%6,%7}, {%8,%9}, {%0,%1,%2,%3};"               \
        : "+f"(c0), "+f"(c1), "+f"(c2), "+f"(c3)                              \
        : "r"(a0), "r"(a1), "r"(a2), "r"(a3), "r"(b0), "r"(b1))

// ---------------------------------------------------------------------------
// Fused tf32 pre-round pass: one launch for all 7 arrays (grid.y selects)
// ---------------------------------------------------------------------------
struct RoundArgs {
    const float* src[7];
    float*       dst[7];
    int          n4[7];
};

__global__ void round_all_kernel(RoundArgs p)
{
    const int y = blockIdx.y;
    const int i = blockIdx.x * blockDim.x + threadIdx.x;
    if (i < p.n4[y]) {
        float4 v = ((const float4*)p.src[y])[i];
        v.x = tf32r(v.x); v.y = tf32r(v.y); v.z = tf32r(v.z); v.w = tf32r(v.w);
        ((float4*)p.dst[y])[i] = v;
    }
}

// ---------------------------------------------------------------------------
// tf32 mma.sync GEMM body: C[M,N] = X[M,K] * W[N,K]^T (+bias).
// 128x128 CTA tile, 512 threads = 16 warps of 32x32, BK=16,
// 4-stage cp.async, 2 CTAs/SM -> 8 warps/SMSP for latency hiding.
// ---------------------------------------------------------------------------
#define BK      16
#define PITCH   20
#define ATILE   (128 * PITCH)
#define STAGEF  (2 * ATILE)
#define NSTAGE  4
#define GEMM_SMEM (NSTAGE * STAGEF * 4) // 81920 bytes (x2 CTAs = 160KB)
#define NCH     (D_MODEL / BK)          // 64 k-chunks

__device__ __forceinline__
void gemm_body(const float* __restrict__ X, const float* __restrict__ W,
               const float* __restrict__ bias, float* __restrict__ C,
               const int addBias, const int roundOut, float* smf)
{
    const int tid  = threadIdx.x;
    const int wid  = tid >> 5;          // 0..15
    const int lane = tid & 31;
    const int g    = lane >> 2;
    const int tig  = lane & 3;
    const int m0 = blockIdx.y * 128;
    const int n0 = blockIdx.x * 128;
    const int wm = (wid >> 2) * 32;     // 0/32/64/96
    const int wn = (wid & 3) * 32;      // 0/32/64/96

    float c[2][4][4];
#pragma unroll
    for (int mt = 0; mt < 2; ++mt)
#pragma unroll
        for (int nt = 0; nt < 4; ++nt)
#pragma unroll
            for (int r = 0; r < 4; ++r) c[mt][nt][r] = 0.f;

    // 1024 x 16B copies per stage, 2 per thread (512 threads)
#define LOAD_STAGE(kt) do {                                                    \
        float* st = smf + ((kt) % NSTAGE) * STAGEF;                            \
        const int k0 = (kt) * BK;                                              \
        _Pragma("unroll")                                                      \
        for (int i = 0; i < 2; ++i) {                                          \
            const int idx  = i * 512 + tid;                                    \
            const int isB  = idx >> 9;                                         \
            const int row  = (idx >> 2) & 127;                                 \
            const int quad = idx & 3;                                          \
            float* dst = st + isB * ATILE + row * PITCH + quad * 4;            \
            const float* src = (isB ? W + (size_t)(n0 + row) * D_MODEL        \
                                    : X + (size_t)(m0 + row) * D_MODEL)       \
                               + k0 + quad * 4;                                \
            CP_ASYNC16(smem_u32(dst), src);                                    \
        }                                                                      \
        CP_COMMIT();                                                           \
    } while (0)

    LOAD_STAGE(0); LOAD_STAGE(1); LOAD_STAGE(2);

    for (int kt = 0; kt < NCH; ++kt) {
        if (kt < NCH - 2)       CP_WAIT(2);
        else if (kt == NCH - 2) CP_WAIT(1);
        else                    CP_WAIT(0);
        __syncthreads();

        if (kt + 3 < NCH) LOAD_STAGE(kt + 3);

        const float* As = smf + (kt % NSTAGE) * STAGEF;
        const float* Bs = As + ATILE;

#pragma unroll
        for (int ks = 0; ks < 2; ++ks) {
            const int kb = ks * 8;
            uint32_t a[2][4], b[4][2];
#pragma unroll
            for (int mt = 0; mt < 2; ++mt) {
                const float* ap = As + (wm + mt * 16 + g) * PITCH + kb + tig;
                a[mt][0] = __float_as_uint(ap[0]);
                a[mt][1] = __float_as_uint(ap[8 * PITCH]);
                a[mt][2] = __float_as_uint(ap[4]);
                a[mt][3] = __float_as_uint(ap[8 * PITCH + 4]);
            }
#pragma unroll
            for (int nt = 0; nt < 4; ++nt) {
                const float* bp = Bs + (wn + nt * 8 + g) * PITCH + kb + tig;
                b[nt][0] = __float_as_uint(bp[0]);
                b[nt][1] = __float_as_uint(bp[4]);
            }
#pragma unroll
            for (int mt = 0; mt < 2; ++mt)
#pragma unroll
                for (int nt = 0; nt < 4; ++nt)
                    MMA_TF32(c[mt][nt][0], c[mt][nt][1], c[mt][nt][2], c[mt][nt][3],
                             a[mt][0], a[mt][1], a[mt][2], a[mt][3],
                             b[nt][0], b[nt][1]);
        }
    }

#pragma unroll
    for (int mt = 0; mt < 2; ++mt) {
        const int row = m0 + wm + mt * 16 + g;
#pragma unroll
        for (int nt = 0; nt < 4; ++nt) {
            const int col = n0 + wn + nt * 8 + 2 * tig;
            float b0 = 0.f, b1 = 0.f;
            if (addBias) { b0 = bias[col]; b1 = bias[col + 1]; }
            float v0 = c[mt][nt][0] + b0, v1 = c[mt][nt][1] + b1;
            float v2 = c[mt][nt][2] + b0, v3 = c[mt][nt][3] + b1;
            if (roundOut) { v0 = tf32r(v0); v1 = tf32r(v1);
                            v2 = tf32r(v2); v3 = tf32r(v3); }
            *(float2*)&C[(size_t)row * D_MODEL + col]       = make_float2(v0, v1);
            *(float2*)&C[(size_t)(row + 8) * D_MODEL + col] = make_float2(v2, v3);
        }
    }
#undef LOAD_STAGE
}

// Fused Q/K/V projection: grid.z selects (X, W, C) triple; outputs tf32-rounded.
struct QKVArgs {
    const float* X[3];
    const float* W[3];
    float*       C[3];
};

__global__ __launch_bounds__(512, 2)
void gemm_qkv(QKVArgs p)
{
    extern __shared__ float smf[];
    const int z = blockIdx.z;
    gemm_body(p.X[z], p.W[z], nullptr, p.C[z], 0, 1, smf);
}

// Output projection: +bias, full fp32 out.
__global__ __launch_bounds__(512, 2)
void gemm_proj(const float* __restrict__ X, const float* __restrict__ W,
               const float* __restrict__ bias, float* __restrict__ C)
{
    extern __shared__ float smf[];
    gemm_body(X, W, bias, C, 1, 0, smf);
}

// ---------------------------------------------------------------------------
// Causal flash attention with mma.sync tf32 + software-pipelined K/V loads.
// (unchanged from the 1010us round)
// ---------------------------------------------------------------------------
#define FP 68
#define FLASH_SMEM (384 * FP * 4)   // Qs 128 + Ks 64 + Vs 64 + Ps 128 rows

__global__ __launch_bounds__(256, 2)
void flash_mma(const float* __restrict__ Q, const float* __restrict__ K,
               const float* __restrict__ V, float* __restrict__ A)
{
    extern __shared__ float sm[];
    float* Qs = sm;                 // [128][FP]
    float* Ks = sm + 128 * FP;      // [64][FP]
    float* Vs = sm + 192 * FP;      // [64][FP]
    float* Ps = sm + 256 * FP;      // [128][FP]

    const int tid  = threadIdx.x;
    const int wid  = tid >> 5;
    const int lane = tid & 31;
    const int g    = lane >> 2;
    const int tig  = lane & 3;
    const int wm   = wid << 4;
    const int qb   = gridDim.x - 1 - blockIdx.x;   // heavy blocks first
    const int bh   = blockIdx.y;
    const int b    = bh >> 4, h = bh & 15;

    const size_t headoff = (size_t)b * SEQ * D_MODEL + (size_t)h * DKH;
    const float* Qh = Q + headoff;
    const float* Kh = K + headoff;
    const float* Vh = V + headoff;

    const int ntile = 2 * qb + 2;
    const int qrow0 = qb * 128 + wm + g;
    const int qrow1 = qrow0 + 8;

    // Preload: Q tile + K(0) in ONE group.
#pragma unroll
    for (int i = 0; i < 8; ++i) {
        const int idx = i * 256 + tid;
        const int r   = idx >> 4;
        const int c4  = (idx & 15) << 2;
        CP_ASYNC16(smem_u32(Qs + r * FP + c4),
                   Qh + (size_t)(qb * 128 + r) * D_MODEL + c4);
    }
#pragma unroll
    for (int i = 0; i < 4; ++i) {
        const int idx = i * 256 + tid;
        const int r   = idx >> 4;
        const int c4  = (idx & 15) << 2;
        CP_ASYNC16(smem_u32(Ks + r * FP + c4),
                   Kh + (size_t)r * D_MODEL + c4);
    }
    CP_COMMIT();

    float oa[8][4];
#pragma unroll
    for (int nt = 0; nt < 8; ++nt)
#pragma unroll
        for (int r = 0; r < 4; ++r) oa[nt][r] = 0.f;
    float mr0 = -1e30f, mr1 = -1e30f, lr0 = 0.f, lr1 = 0.f;

    for (int t = 0; t < ntile; ++t) {
        CP_WAIT(0);
        __syncthreads();

        // issue V(t) — overlaps with S-mma + softmax below
#pragma unroll
        for (int i = 0; i < 4; ++i) {
            const int idx = i * 256 + tid;
            const int r   = idx >> 4;
            const int c4  = (idx & 15) << 2;
            CP_ASYNC16(smem_u32(Vs + r * FP + c4),
                       Vh + (size_t)(t * 64 + r) * D_MODEL + c4);
        }
        CP_COMMIT();

        // ---- S = Q K^T ----
        float sacc[8][4];
#pragma unroll
        for (int nt = 0; nt < 8; ++nt)
#pragma unroll
            for (int r = 0; r < 4; ++r) sacc[nt][r] = 0.f;

#pragma unroll
        for (int ks = 0; ks < 8; ++ks) {
            const float* ap = Qs + (wm + g) * FP + ks * 8 + tig;
            const uint32_t a0 = __float_as_uint(ap[0]);
            const uint32_t a1 = __float_as_uint(ap[8 * FP]);
            const uint32_t a2 = __float_as_uint(ap[4]);
            const uint32_t a3 = __float_as_uint(ap[8 * FP + 4]);
#pragma unroll
            for (int nt = 0; nt < 8; ++nt) {
                const float* bp = Ks + (nt * 8 + g) * FP + ks * 8 + tig;
                const uint32_t b0 = __float_as_uint(bp[0]);
                const uint32_t b1 = __float_as_uint(bp[4]);
                MMA_TF32(sacc[nt][0], sacc[nt][1], sacc[nt][2], sacc[nt][3],
                         a0, a1, a2, a3, b0, b1);
            }
        }

        // ---- scale + causal mask (last two tiles only) ----
        const bool tail = (t >= 2 * qb);
        const int cb = t * 64 + 2 * tig;
        float mx0 = -1e30f, mx1 = -1e30f;
#pragma unroll
        for (int nt = 0; nt < 8; ++nt) {
            const int c0 = cb + nt * 8, c1 = c0 + 1;
            float v0 = sacc[nt][0] * 0.125f;
            float v1 = sacc[nt][1] * 0.125f;
            float v2 = sacc[nt][2] * 0.125f;
            float v3 = sacc[nt][3] * 0.125f;
            if (tail) {
                if (c0 > qrow0) v0 = -1e30f;
                if (c1 > qrow0) v1 = -1e30f;
                if (c0 > qrow1) v2 = -1e30f;
                if (c1 > qrow1) v3 = -1e30f;
            }
            sacc[nt][0] = v0; sacc[nt][1] = v1;
            sacc[nt][2] = v2; sacc[nt][3] = v3;
            mx0 = fmaxf(mx0, fmaxf(v0, v1));
            mx1 = fmaxf(mx1, fmaxf(v2, v3));
        }
        mx0 = fmaxf(mx0, __shfl_xor_sync(0xffffffffu, mx0, 1));
        mx0 = fmaxf(mx0, __shfl_xor_sync(0xffffffffu, mx0, 2));
        mx1 = fmaxf(mx1, __shfl_xor_sync(0xffffffffu, mx1, 1));
        mx1 = fmaxf(mx1, __shfl_xor_sync(0xffffffffu, mx1, 2));

        const float mn0 = fmaxf(mr0, mx0);
        const float mn1 = fmaxf(mr1, mx1);
        const float co0 = __expf(mr0 - mn0);
        const float co1 = __expf(mr1 - mn1);
        mr0 = mn0; mr1 = mn1;

        float rs0 = 0.f, rs1 = 0.f;
        float* pr0 = Ps + (wm + g) * FP + 2 * tig;
        float* pr1 = pr0 + 8 * FP;
#pragma unroll
        for (int nt = 0; nt < 8; ++nt) {
            const float p0 = __expf(sacc[nt][0] - mn0);
            const float p1 = __expf(sacc[nt][1] - mn0);
            const float p2 = __expf(sacc[nt][2] - mn1);
            const float p3 = __expf(sacc[nt][3] - mn1);
            rs0 += p0 + p1; rs1 += p2 + p3;
            *(float2*)(pr0 + nt * 8) = make_float2(tf32r(p0), tf32r(p1));
            *(float2*)(pr1 + nt * 8) = make_float2(tf32r(p2), tf32r(p3));
        }
        rs0 += __shfl_xor_sync(0xffffffffu, rs0, 1);
        rs0 += __shfl_xor_sync(0xffffffffu, rs0, 2);
        rs1 += __shfl_xor_sync(0xffffffffu, rs1, 1);
        rs1 += __shfl_xor_sync(0xffffffffu, rs1, 2);
        lr0 = lr0 * co0 + rs0;
        lr1 = lr1 * co1 + rs1;

#pragma unroll
        for (int nt = 0; nt < 8; ++nt) {
            oa[nt][0] *= co0; oa[nt][1] *= co0;
            oa[nt][2] *= co1; oa[nt][3] *= co1;
        }
        __syncwarp();

        __syncthreads();    // all warps done reading Ks -> Ks writable

        // issue K(t+1) — overlaps with PV below
        if (t + 1 < ntile) {
#pragma unroll
            for (int i = 0; i < 4; ++i) {
                const int idx = i * 256 + tid;
                const int r   = idx >> 4;
                const int c4  = (idx & 15) << 2;
                CP_ASYNC16(smem_u32(Ks + r * FP + c4),
                           Kh + (size_t)((t + 1) * 64 + r) * D_MODEL + c4);
            }
            CP_COMMIT();
            CP_WAIT(1);
        } else {
            CP_WAIT(0);
        }
        __syncthreads();

        // ---- O += P V ----
#pragma unroll
        for (int ks = 0; ks < 8; ++ks) {
            const float* ap = Ps + (wm + g) * FP + ks * 8 + tig;
            const uint32_t a0 = __float_as_uint(ap[0]);
            const uint32_t a1 = __float_as_uint(ap[8 * FP]);
            const uint32_t a2 = __float_as_uint(ap[4]);
            const uint32_t a3 = __float_as_uint(ap[8 * FP + 4]);
#pragma unroll
            for (int nt = 0; nt < 8; ++nt) {
                const float* bp = Vs + (ks * 8 + tig) * FP + nt * 8 + g;
                const uint32_t b0 = __float_as_uint(bp[0]);
                const uint32_t b1 = __float_as_uint(bp[4 * FP]);
                MMA_TF32(oa[nt][0], oa[nt][1], oa[nt][2], oa[nt][3],
                         a0, a1, a2, a3, b0, b1);
            }
        }
    }

    // ---- epilogue: normalize + tf32-round (final GEMM consumes this) ----
    const float inv0 = 1.f / lr0;
    const float inv1 = 1.f / lr1;
    float* Ar0 = (float*)(A + headoff + (size_t)qrow0 * D_MODEL);
    float* Ar1 = (float*)(A + headoff + (size_t)qrow1 * D_MODEL);
#pragma unroll
    for (int nt = 0; nt < 8; ++nt) {
        const int col = nt * 8 + 2 * tig;
        *(float2*)(Ar0 + col) = make_float2(tf32r(oa[nt][0] * inv0),
                                            tf32r(oa[nt][1] * inv0));
        *(float2*)(Ar1 + col) = make_float2(tf32r(oa[nt][2] * inv1),
                                            tf32r(oa[nt][3] * inv1));
    }
}

// ---------------------------------------------------------------------------
extern "C" void kernel_launch(void* const* d_in, const int* in_sizes, int n_in,
                              void* d_out, int out_size)
{
    const float* xq = (const float*)d_in[0];
    const float* xk = (const float*)d_in[1];
    const float* xv = (const float*)d_in[2];
    const float* wq = (const float*)d_in[3];
    const float* wk = (const float*)d_in[4];
    const float* wv = (const float*)d_in[5];
    const float* wp = (const float*)d_in[6];
    const float* bp = (const float*)d_in[7];
    float* out = (float*)d_out;

    float *gq, *gk, *gv, *ga, *rxq, *rxk, *rxv, *rwq, *rwk, *rwv, *rwp;
    cudaGetSymbolAddress((void**)&gq,  g_q);
    cudaGetSymbolAddress((void**)&gk,  g_k);
    cudaGetSymbolAddress((void**)&gv,  g_v);
    cudaGetSymbolAddress((void**)&ga,  g_a);
    cudaGetSymbolAddress((void**)&rxq, g_rxq);
    cudaGetSymbolAddress((void**)&rxk, g_rxk);
    cudaGetSymbolAddress((void**)&rxv, g_rxv);
    cudaGetSymbolAddress((void**)&rwq, g_rwq);
    cudaGetSymbolAddress((void**)&rwk, g_rwk);
    cudaGetSymbolAddress((void**)&rwv, g_rwv);
    cudaGetSymbolAddress((void**)&rwp, g_rwp);

    cudaFuncSetAttribute(gemm_qkv,
                         cudaFuncAttributeMaxDynamicSharedMemorySize, GEMM_SMEM);
    cudaFuncSetAttribute(gemm_proj,
                         cudaFuncAttributeMaxDynamicSharedMemorySize, GEMM_SMEM);
    cudaFuncSetAttribute(flash_mma,
                         cudaFuncAttributeMaxDynamicSharedMemorySize, FLASH_SMEM);

    const int nx4 = MROWS * D_MODEL / 4;     // 2097152
    const int nw4 = D_MODEL * D_MODEL / 4;   // 262144

    RoundArgs ra;
    ra.src[0] = xq; ra.dst[0] = rxq; ra.n4[0] = nx4;
    ra.src[1] = xk; ra.dst[1] = rxk; ra.n4[1] = nx4;
    ra.src[2] = xv; ra.dst[2] = rxv; ra.n4[2] = nx4;
    ra.src[3] = wq; ra.dst[3] = rwq; ra.n4[3] = nw4;
    ra.src[4] = wk; ra.dst[4] = rwk; ra.n4[4] = nw4;
    ra.src[5] = wv; ra.dst[5] = rwv; ra.n4[5] = nw4;
    ra.src[6] = wp; ra.dst[6] = rwp; ra.n4[6] = nw4;
    round_all_kernel<<<dim3(nx4 / 256, 7), 256>>>(ra);

    QKVArgs qa;
    qa.X[0] = rxq; qa.W[0] = rwq; qa.C[0] = gq;
    qa.X[1] = rxk; qa.W[1] = rwk; qa.C[1] = gk;
    qa.X[2] = rxv; qa.W[2] = rwv; qa.C[2] = gv;
    gemm_qkv<<<dim3(D_MODEL / 128, MROWS / 128, 3), 512, GEMM_SMEM>>>(qa);

    flash_mma<<<dim3(SEQ / 128, BATCH * NH), 256, FLASH_SMEM>>>(gq, gk, gv, ga);

    gemm_proj<<<dim3(D_MODEL / 128, MROWS / 128), 512, GEMM_SMEM>>>(ga, rwp, bp, out);
}

// round 16
// speedup vs baseline: 3.3893x; 1.1157x over previous
#include <cuda_runtime.h>
#include <cuda_bf16.h>
#include <cstdint>
#include <math.h>

// Problem constants
#define D_MODEL 1024
#define DKH     64
#define NH      16
#define BATCH   4
#define SEQ     2048
#define MROWS   (BATCH * SEQ)   // 8192

// Scratch (device globals: allocation-free per harness rules)
__device__ float g_q[(size_t)MROWS * D_MODEL];
__device__ float g_k[(size_t)MROWS * D_MODEL];
__device__ float g_v[(size_t)MROWS * D_MODEL];
__device__ float g_a[(size_t)MROWS * D_MODEL];
// tf32-rounded GEMM inputs
__device__ float g_rxq[(size_t)MROWS * D_MODEL];
__device__ float g_rxk[(size_t)MROWS * D_MODEL];
__device__ float g_rxv[(size_t)MROWS * D_MODEL];
__device__ float g_rwq[(size_t)D_MODEL * D_MODEL];
__device__ float g_rwk[(size_t)D_MODEL * D_MODEL];
__device__ float g_rwv[(size_t)D_MODEL * D_MODEL];
__device__ float g_rwp[(size_t)D_MODEL * D_MODEL];

// ---------------------------------------------------------------------------
// Helpers (baseline PTX only — harness compiles at compute_103)
// ---------------------------------------------------------------------------
__device__ __forceinline__ uint32_t smem_u32(const void* p) {
    uint32_t a;
    asm("{ .reg .u64 t; cvta.to.shared.u64 t, %1; cvt.u32.u64 %0, t; }"
        : "=r"(a) : "l"(p));
    return a;
}
__device__ __forceinline__ float tf32r(float x) {
    uint32_t u;
    asm("cvt.rna.tf32.f32 %0, %1;" : "=r"(u) : "f"(x));
    return __uint_as_float(u);
}

#define CP_ASYNC16(dst, src) \
    asm volatile("cp.async.cg.shared.global [%0], [%1], 16;" :: "r"(dst), "l"(src))
#define CP_COMMIT() asm volatile("cp.async.commit_group;")
#define CP_WAIT(n)  asm volatile("cp.async.wait_group %0;" :: "n"(n))

// mma.sync m16n8k8 tf32: D = A*B + C (A row-major 16x8, B col-major 8x8)
#define MMA_TF32(c0, c1, c2, c3, a0, a1, a2, a3, b0, b1)                      \
    asm volatile(                                                             \
        "mma.sync.aligned.m16n8k8.row.col.f32.tf32.tf32.f32 "                 \
        "{%0,%1,%2,%3}, {%4,%5,%6,%7}, {%8,%9}, {%0,%1,%2,%3};"               \
        : "+f"(c0), "+f"(c1), "+f"(c2), "+f"(c3)                              \
        : "r"(a0), "r"(a1), "r"(a2), "r"(a3), "r"(b0), "r"(b1))

// ldmatrix x4 (b16 tiles; one 8x4-tf32 tile per 8 address lanes).
// Lanes 0-7 -> r0's tile rows, 8-15 -> r1, 16-23 -> r2, 24-31 -> r3.
#define LDSM_X4(r0, r1, r2, r3, addr)                                         \
    asm volatile(                                                             \
        "ldmatrix.sync.aligned.m8n8.x4.shared.b16 {%0,%1,%2,%3}, [%4];"       \
        : "=r"(r0), "=r"(r1), "=r"(r2), "=r"(r3) : "r"(addr))

// ---------------------------------------------------------------------------
// Fused tf32 pre-round pass: one launch for all 7 arrays (grid.y selects)
// ---------------------------------------------------------------------------
struct RoundArgs {
    const float* src[7];
    float*       dst[7];
    int          n4[7];
};

__global__ void round_all_kernel(RoundArgs p)
{
    const int y = blockIdx.y;
    const int i = blockIdx.x * blockDim.x + threadIdx.x;
    if (i < p.n4[y]) {
        float4 v = ((const float4*)p.src[y])[i];
        v.x = tf32r(v.x); v.y = tf32r(v.y); v.z = tf32r(v.z); v.w = tf32r(v.w);
        ((float4*)p.dst[y])[i] = v;
    }
}

// ---------------------------------------------------------------------------
// tf32 mma.sync GEMM body: C[M,N] = X[M,K] * W[N,K]^T (+bias).
// 128x128 CTA tile, 512 threads = 16 warps of 32x32, BK=16, 4-stage cp.async.
// Fragment loads via ldmatrix.x4 (PITCH=20 -> conflict-free LDSM phases).
// ---------------------------------------------------------------------------
#define BK      16
#define PITCH   20
#define ATILE   (128 * PITCH)
#define STAGEF  (2 * ATILE)
#define NSTAGE  4
#define GEMM_SMEM (NSTAGE * STAGEF * 4) // 81920 bytes (x2 CTAs = 160KB)
#define NCH     (D_MODEL / BK)          // 64 k-chunks

__device__ __forceinline__
void gemm_body(const float* __restrict__ X, const float* __restrict__ W,
               const float* __restrict__ bias, float* __restrict__ C,
               const int addBias, const int roundOut, float* smf)
{
    const int tid  = threadIdx.x;
    const int wid  = tid >> 5;          // 0..15
    const int lane = tid & 31;
    const int g    = lane >> 2;
    const int tig  = lane & 3;
    const int m0 = blockIdx.y * 128;
    const int n0 = blockIdx.x * 128;
    const int wm = (wid >> 2) * 32;     // 0/32/64/96
    const int wn = (wid & 3) * 32;      // 0/32/64/96

    float c[2][4][4];
#pragma unroll
    for (int mt = 0; mt < 2; ++mt)
#pragma unroll
        for (int nt = 0; nt < 4; ++nt)
#pragma unroll
            for (int r = 0; r < 4; ++r) c[mt][nt][r] = 0.f;

    // Per-thread ldmatrix byte offsets (within a stage):
    //   A tile mt: rows wm+mt*16+(lane&15), float col (lane>>4)*4
    //   B pair j : rows wn+(2j+(lane>>4))*8+(lane&7), float col ((lane>>3)&1)*4
    const uint32_t sb0 = smem_u32(smf);
    uint32_t aoff[2], boff[2];
#pragma unroll
    for (int mt = 0; mt < 2; ++mt)
        aoff[mt] = ((wm + mt * 16 + (lane & 15)) * PITCH + ((lane >> 4) << 2)) * 4;
#pragma unroll
    for (int j = 0; j < 2; ++j)
        boff[j] = (ATILE + (wn + (2 * j + (lane >> 4)) * 8 + (lane & 7)) * PITCH
                   + (((lane >> 3) & 1) << 2)) * 4;

    // 1024 x 16B copies per stage, 2 per thread (512 threads)
#define LOAD_STAGE(kt) do {                                                    \
        float* st = smf + ((kt) % NSTAGE) * STAGEF;                            \
        const int k0 = (kt) * BK;                                              \
        _Pragma("unroll")                                                      \
        for (int i = 0; i < 2; ++i) {                                          \
            const int idx  = i * 512 + tid;                                    \
            const int isB  = idx >> 9;                                         \
            const int row  = (idx >> 2) & 127;                                 \
            const int quad = idx & 3;                                          \
            float* dst = st + isB * ATILE + row * PITCH + quad * 4;            \
            const float* src = (isB ? W + (size_t)(n0 + row) * D_MODEL        \
                                    : X + (size_t)(m0 + row) * D_MODEL)       \
                               + k0 + quad * 4;                                \
            CP_ASYNC16(smem_u32(dst), src);                                    \
        }                                                                      \
        CP_COMMIT();                                                           \
    } while (0)

    LOAD_STAGE(0); LOAD_STAGE(1); LOAD_STAGE(2);

    for (int kt = 0; kt < NCH; ++kt) {
        if (kt < NCH - 2)       CP_WAIT(2);
        else if (kt == NCH - 2) CP_WAIT(1);
        else                    CP_WAIT(0);
        __syncthreads();

        if (kt + 3 < NCH) LOAD_STAGE(kt + 3);

        const uint32_t stb = sb0 + (uint32_t)(kt % NSTAGE) * (STAGEF * 4);

#pragma unroll
        for (int ks = 0; ks < 2; ++ks) {
            const uint32_t kbb = ks * 32;   // 8 floats
            uint32_t a[2][4], b[2][4];
#pragma unroll
            for (int mt = 0; mt < 2; ++mt)
                LDSM_X4(a[mt][0], a[mt][1], a[mt][2], a[mt][3],
                        stb + aoff[mt] + kbb);
#pragma unroll
            for (int j = 0; j < 2; ++j)
                LDSM_X4(b[j][0], b[j][1], b[j][2], b[j][3],
                        stb + boff[j] + kbb);
#pragma unroll
            for (int mt = 0; mt < 2; ++mt)
#pragma unroll
                for (int j = 0; j < 2; ++j) {
                    MMA_TF32(c[mt][2*j][0], c[mt][2*j][1], c[mt][2*j][2], c[mt][2*j][3],
                             a[mt][0], a[mt][1], a[mt][2], a[mt][3],
                             b[j][0], b[j][1]);
                    MMA_TF32(c[mt][2*j+1][0], c[mt][2*j+1][1], c[mt][2*j+1][2], c[mt][2*j+1][3],
                             a[mt][0], a[mt][1], a[mt][2], a[mt][3],
                             b[j][2], b[j][3]);
                }
        }
    }

#pragma unroll
    for (int mt = 0; mt < 2; ++mt) {
        const int row = m0 + wm + mt * 16 + g;
#pragma unroll
        for (int nt = 0; nt < 4; ++nt) {
            const int col = n0 + wn + nt * 8 + 2 * tig;
            float b0 = 0.f, b1 = 0.f;
            if (addBias) { b0 = bias[col]; b1 = bias[col + 1]; }
            float v0 = c[mt][nt][0] + b0, v1 = c[mt][nt][1] + b1;
            float v2 = c[mt][nt][2] + b0, v3 = c[mt][nt][3] + b1;
            if (roundOut) { v0 = tf32r(v0); v1 = tf32r(v1);
                            v2 = tf32r(v2); v3 = tf32r(v3); }
            *(float2*)&C[(size_t)row * D_MODEL + col]       = make_float2(v0, v1);
            *(float2*)&C[(size_t)(row + 8) * D_MODEL + col] = make_float2(v2, v3);
        }
    }
#undef LOAD_STAGE
}

// Fused Q/K/V projection: grid.z selects (X, W, C) triple; outputs tf32-rounded.
struct QKVArgs {
    const float* X[3];
    const float* W[3];
    float*       C[3];
};

__global__ __launch_bounds__(512, 2)
void gemm_qkv(QKVArgs p)
{
    extern __shared__ float smf[];
    const int z = blockIdx.z;
    gemm_body(p.X[z], p.W[z], nullptr, p.C[z], 0, 1, smf);
}

// Output projection: +bias, full fp32 out.
__global__ __launch_bounds__(512, 2)
void gemm_proj(const float* __restrict__ X, const float* __restrict__ W,
               const float* __restrict__ bias, float* __restrict__ C)
{
    extern __shared__ float smf[];
    gemm_body(X, W, bias, C, 1, 0, smf);
}

// ---------------------------------------------------------------------------
// Causal flash attention, mma.sync tf32, pipelined K/V, ldmatrix fragments.
// ---------------------------------------------------------------------------
#define FP 68
#define FLASH_SMEM (384 * FP * 4)   // Qs 128 + Ks 64 + Vs 64 + Ps 128 rows

__global__ __launch_bounds__(256, 2)
void flash_mma(const float* __restrict__ Q, const float* __restrict__ K,
               const float* __restrict__ V, float* __restrict__ A)
{
    extern __shared__ float sm[];
    float* Qs = sm;                 // [128][FP]
    float* Ks = sm + 128 * FP;      // [64][FP]
    float* Vs = sm + 192 * FP;      // [64][FP]
    float* Ps = sm + 256 * FP;      // [128][FP]

    const int tid  = threadIdx.x;
    const int wid  = tid >> 5;
    const int lane = tid & 31;
    const int g    = lane >> 2;
    const int tig  = lane & 3;
    const int wm   = wid << 4;
    const int qb   = gridDim.x - 1 - blockIdx.x;   // heavy blocks first
    const int bh   = blockIdx.y;
    const int b    = bh >> 4, h = bh & 15;

    const size_t headoff = (size_t)b * SEQ * D_MODEL + (size_t)h * DKH;
    const float* Qh = Q + headoff;
    const float* Kh = K + headoff;
    const float* Vh = V + headoff;

    const int ntile = 2 * qb + 2;
    const int qrow0 = qb * 128 + wm + g;
    const int qrow1 = qrow0 + 8;

    // ldmatrix base addresses (byte):
    //   Q/P A-frag: rows wm+(lane&15), float col (lane>>4)*4
    //   K  B-frag pair j: rows (2j+(lane>>4))*8+(lane&7), col ((lane>>3)&1)*4
    const uint32_t qa_base = smem_u32(Qs)
        + ((wm + (lane & 15)) * FP + ((lane >> 4) << 2)) * 4;
    const uint32_t pa_base = smem_u32(Ps)
        + ((wm + (lane & 15)) * FP + ((lane >> 4) << 2)) * 4;
    uint32_t kb_base[4];
#pragma unroll
    for (int j = 0; j < 4; ++j)
        kb_base[j] = smem_u32(Ks)
            + (((2 * j + (lane >> 4)) * 8 + (lane & 7)) * FP
               + (((lane >> 3) & 1) << 2)) * 4;

    // Preload: Q tile + K(0) in ONE group.
#pragma unroll
    for (int i = 0; i < 8; ++i) {
        const int idx = i * 256 + tid;
        const int r   = idx >> 4;
        const int c4  = (idx & 15) << 2;
        CP_ASYNC16(smem_u32(Qs + r * FP + c4),
                   Qh + (size_t)(qb * 128 + r) * D_MODEL + c4);
    }
#pragma unroll
    for (int i = 0; i < 4; ++i) {
        const int idx = i * 256 + tid;
        const int r   = idx >> 4;
        const int c4  = (idx & 15) << 2;
        CP_ASYNC16(smem_u32(Ks + r * FP + c4),
                   Kh + (size_t)r * D_MODEL + c4);
    }
    CP_COMMIT();

    float oa[8][4];
#pragma unroll
    for (int nt = 0; nt < 8; ++nt)
#pragma unroll
        for (int r = 0; r < 4; ++r) oa[nt][r] = 0.f;
    float mr0 = -1e30f, mr1 = -1e30f, lr0 = 0.f, lr1 = 0.f;

    for (int t = 0; t < ntile; ++t) {
        CP_WAIT(0);
        __syncthreads();

        // issue V(t) — overlaps with S-mma + softmax below
#pragma unroll
        for (int i = 0; i < 4; ++i) {
            const int idx = i * 256 + tid;
            const int r   = idx >> 4;
            const int c4  = (idx & 15) << 2;
            CP_ASYNC16(smem_u32(Vs + r * FP + c4),
                       Vh + (size_t)(t * 64 + r) * D_MODEL + c4);
        }
        CP_COMMIT();

        // ---- S = Q K^T ----
        float sacc[8][4];
#pragma unroll
        for (int nt = 0; nt < 8; ++nt)
#pragma unroll
            for (int r = 0; r < 4; ++r) sacc[nt][r] = 0.f;

#pragma unroll
        for (int ks = 0; ks < 8; ++ks) {
            const uint32_t kbb = ks * 32;
            uint32_t a0, a1, a2, a3;
            LDSM_X4(a0, a1, a2, a3, qa_base + kbb);
#pragma unroll
            for (int j = 0; j < 4; ++j) {
                uint32_t b0, b1, b2, b3;
                LDSM_X4(b0, b1, b2, b3, kb_base[j] + kbb);
                MMA_TF32(sacc[2*j][0], sacc[2*j][1], sacc[2*j][2], sacc[2*j][3],
                         a0, a1, a2, a3, b0, b1);
                MMA_TF32(sacc[2*j+1][0], sacc[2*j+1][1], sacc[2*j+1][2], sacc[2*j+1][3],
                         a0, a1, a2, a3, b2, b3);
            }
        }

        // ---- scale + causal mask (last two tiles only) ----
        const bool tail = (t >= 2 * qb);
        const int cb = t * 64 + 2 * tig;
        float mx0 = -1e30f, mx1 = -1e30f;
#pragma unroll
        for (int nt = 0; nt < 8; ++nt) {
            const int c0 = cb + nt * 8, c1 = c0 + 1;
            float v0 = sacc[nt][0] * 0.125f;
            float v1 = sacc[nt][1] * 0.125f;
            float v2 = sacc[nt][2] * 0.125f;
            float v3 = sacc[nt][3] * 0.125f;
            if (tail) {
                if (c0 > qrow0) v0 = -1e30f;
                if (c1 > qrow0) v1 = -1e30f;
                if (c0 > qrow1) v2 = -1e30f;
                if (c1 > qrow1) v3 = -1e30f;
            }
            sacc[nt][0] = v0; sacc[nt][1] = v1;
            sacc[nt][2] = v2; sacc[nt][3] = v3;
            mx0 = fmaxf(mx0, fmaxf(v0, v1));
            mx1 = fmaxf(mx1, fmaxf(v2, v3));
        }
        mx0 = fmaxf(mx0, __shfl_xor_sync(0xffffffffu, mx0, 1));
        mx0 = fmaxf(mx0, __shfl_xor_sync(0xffffffffu, mx0, 2));
        mx1 = fmaxf(mx1, __shfl_xor_sync(0xffffffffu, mx1, 1));
        mx1 = fmaxf(mx1, __shfl_xor_sync(0xffffffffu, mx1, 2));

        const float mn0 = fmaxf(mr0, mx0);
        const float mn1 = fmaxf(mr1, mx1);
        const float co0 = __expf(mr0 - mn0);
        const float co1 = __expf(mr1 - mn1);
        mr0 = mn0; mr1 = mn1;

        float rs0 = 0.f, rs1 = 0.f;
        float* pr0 = Ps + (wm + g) * FP + 2 * tig;
        float* pr1 = pr0 + 8 * FP;
#pragma unroll
        for (int nt = 0; nt < 8; ++nt) {
            const float p0 = __expf(sacc[nt][0] - mn0);
            const float p1 = __expf(sacc[nt][1] - mn0);
            const float p2 = __expf(sacc[nt][2] - mn1);
            const float p3 = __expf(sacc[nt][3] - mn1);
            rs0 += p0 + p1; rs1 += p2 + p3;
            *(float2*)(pr0 + nt * 8) = make_float2(tf32r(p0), tf32r(p1));
            *(float2*)(pr1 + nt * 8) = make_float2(tf32r(p2), tf32r(p3));
        }
        rs0 += __shfl_xor_sync(0xffffffffu, rs0, 1);
        rs0 += __shfl_xor_sync(0xffffffffu, rs0, 2);
        rs1 += __shfl_xor_sync(0xffffffffu, rs1, 1);
        rs1 += __shfl_xor_sync(0xffffffffu, rs1, 2);
        lr0 = lr0 * co0 + rs0;
        lr1 = lr1 * co1 + rs1;

#pragma unroll
        for (int nt = 0; nt < 8; ++nt) {
            oa[nt][0] *= co0; oa[nt][1] *= co0;
            oa[nt][2] *= co1; oa[nt][3] *= co1;
        }
        __syncwarp();       // P stores visible to own warp (LDSM reads below)

        __syncthreads();    // all warps done reading Ks -> Ks writable

        // issue K(t+1) — overlaps with PV below
        if (t + 1 < ntile) {
#pragma unroll
            for (int i = 0; i < 4; ++i) {
                const int idx = i * 256 + tid;
                const int r   = idx >> 4;
                const int c4  = (idx & 15) << 2;
                CP_ASYNC16(smem_u32(Ks + r * FP + c4),
                           Kh + (size_t)((t + 1) * 64 + r) * D_MODEL + c4);
            }
            CP_COMMIT();
            CP_WAIT(1);
        } else {
            CP_WAIT(0);
        }
        __syncthreads();

        // ---- O += P V ----
#pragma unroll
        for (int ks = 0; ks < 8; ++ks) {
            uint32_t a0, a1, a2, a3;
            LDSM_X4(a0, a1, a2, a3, pa_base + ks * 32);
#pragma unroll
            for (int nt = 0; nt < 8; ++nt) {
                const float* bp = Vs + (ks * 8 + tig) * FP + nt * 8 + g;
                const uint32_t b0 = __float_as_uint(bp[0]);
                const uint32_t b1 = __float_as_uint(bp[4 * FP]);
                MMA_TF32(oa[nt][0], oa[nt][1], oa[nt][2], oa[nt][3],
                         a0, a1, a2, a3, b0, b1);
            }
        }
    }

    // ---- epilogue: normalize + tf32-round (final GEMM consumes this) ----
    const float inv0 = 1.f / lr0;
    const float inv1 = 1.f / lr1;
    float* Ar0 = (float*)(A + headoff + (size_t)qrow0 * D_MODEL);
    float* Ar1 = (float*)(A + headoff + (size_t)qrow1 * D_MODEL);
#pragma unroll
    for (int nt = 0; nt < 8; ++nt) {
        const int col = nt * 8 + 2 * tig;
        *(float2*)(Ar0 + col) = make_float2(tf32r(oa[nt][0] * inv0),
                                            tf32r(oa[nt][1] * inv0));
        *(float2*)(Ar1 + col) = make_float2(tf32r(oa[nt][2] * inv1),
                                            tf32r(oa[nt][3] * inv1));
    }
}

// ---------------------------------------------------------------------------
extern "C" void kernel_launch(void* const* d_in, const int* in_sizes, int n_in,
                              void* d_out, int out_size)
{
    const float* xq = (const float*)d_in[0];
    const float* xk = (const float*)d_in[1];
    const float* xv = (const float*)d_in[2];
    const float* wq = (const float*)d_in[3];
    const float* wk = (const float*)d_in[4];
    const float* wv = (const float*)d_in[5];
    const float* wp = (const float*)d_in[6];
    const float* bp = (const float*)d_in[7];
    float* out = (float*)d_out;

    float *gq, *gk, *gv, *ga, *rxq, *rxk, *rxv, *rwq, *rwk, *rwv, *rwp;
    cudaGetSymbolAddress((void**)&gq,  g_q);
    cudaGetSymbolAddress((void**)&gk,  g_k);
    cudaGetSymbolAddress((void**)&gv,  g_v);
    cudaGetSymbolAddress((void**)&ga,  g_a);
    cudaGetSymbolAddress((void**)&rxq, g_rxq);
    cudaGetSymbolAddress((void**)&rxk, g_rxk);
    cudaGetSymbolAddress((void**)&rxv, g_rxv);
    cudaGetSymbolAddress((void**)&rwq, g_rwq);
    cudaGetSymbolAddress((void**)&rwk, g_rwk);
    cudaGetSymbolAddress((void**)&rwv, g_rwv);
    cudaGetSymbolAddress((void**)&rwp, g_rwp);

    cudaFuncSetAttribute(gemm_qkv,
                         cudaFuncAttributeMaxDynamicSharedMemorySize, GEMM_SMEM);
    cudaFuncSetAttribute(gemm_proj,
                         cudaFuncAttributeMaxDynamicSharedMemorySize, GEMM_SMEM);
    cudaFuncSetAttribute(flash_mma,
                         cudaFuncAttributeMaxDynamicSharedMemorySize, FLASH_SMEM);

    const int nx4 = MROWS * D_MODEL / 4;     // 2097152
    const int nw4 = D_MODEL * D_MODEL / 4;   // 262144

    RoundArgs ra;
    ra.src[0] = xq; ra.dst[0] = rxq; ra.n4[0] = nx4;
    ra.src[1] = xk; ra.dst[1] = rxk; ra.n4[1] = nx4;
    ra.src[2] = xv; ra.dst[2] = rxv; ra.n4[2] = nx4;
    ra.src[3] = wq; ra.dst[3] = rwq; ra.n4[3] = nw4;
    ra.src[4] = wk; ra.dst[4] = rwk; ra.n4[4] = nw4;
    ra.src[5] = wv; ra.dst[5] = rwv; ra.n4[5] = nw4;
    ra.src[6] = wp; ra.dst[6] = rwp; ra.n4[6] = nw4;
    round_all_kernel<<<dim3(nx4 / 256, 7), 256>>>(ra);

    QKVArgs qa;
    qa.X[0] = rxq; qa.W[0] = rwq; qa.C[0] = gq;
    qa.X[1] = rxk; qa.W[1] = rwk; qa.C[1] = gk;
    qa.X[2] = rxv; qa.W[2] = rwv; qa.C[2] = gv;
    gemm_qkv<<<dim3(D_MODEL / 128, MROWS / 128, 3), 512, GEMM_SMEM>>>(qa);

    flash_mma<<<dim3(SEQ / 128, BATCH * NH), 256, FLASH_SMEM>>>(gq, gk, gv, ga);

    gemm_proj<<<dim3(D_MODEL / 128, MROWS / 128), 512, GEMM_SMEM>>>(ga, rwp, bp, out);
}